// round 1
// baseline (speedup 1.0000x reference)
#include <cuda_runtime.h>
#include <math.h>

#define N_NODES 50000
#define N_EDGES 800000
#define IN_F    128
#define HC      256
#define G_GRAPHS 64
#define OUT_F   64
#define NLAYERS 4

// ---------------- scratch (static device allocations; no cudaMalloc) ----------------
__device__ float g_qkvs[(size_t)N_NODES * 1024];   // [q|k|v|s] per node, 204.8 MB
__device__ float g_h[(size_t)N_NODES * HC];        // layer activations
__device__ float g_Wc[256 * 1024];                 // packed [F,1024] weights for current layer
__device__ float g_bc[1024];
__device__ int   g_cnt[N_NODES];
__device__ int   g_cur[N_NODES];
__device__ int   g_off[N_NODES + 1];
__device__ int   g_psrc[N_EDGES];
__device__ float g_pool[G_GRAPHS * HC];
__device__ int   g_gcnt[G_GRAPHS];

// ---------------- CSR build ----------------
__global__ void zero_csr_kernel() {
    int i = blockIdx.x * blockDim.x + threadIdx.x;
    if (i < N_NODES) { g_cnt[i] = 0; g_cur[i] = 0; }
}

__global__ void hist_kernel(const int* __restrict__ dst) {
    int e = blockIdx.x * blockDim.x + threadIdx.x;
    if (e < N_EDGES) atomicAdd(&g_cnt[dst[e]], 1);
}

__global__ void scan_kernel() {
    __shared__ int buf[1024];
    __shared__ int carry;
    int tid = threadIdx.x;
    if (tid == 0) carry = 0;
    __syncthreads();
    for (int base = 0; base < N_NODES; base += 1024) {
        int i = base + tid;
        int v = (i < N_NODES) ? g_cnt[i] : 0;
        buf[tid] = v;
        __syncthreads();
        #pragma unroll
        for (int ofs = 1; ofs < 1024; ofs <<= 1) {
            int t = (tid >= ofs) ? buf[tid - ofs] : 0;
            __syncthreads();
            buf[tid] += t;
            __syncthreads();
        }
        int excl = buf[tid] - v + carry;
        if (i < N_NODES) g_off[i] = excl;
        __syncthreads();
        if (tid == 1023) carry += buf[1023];
        __syncthreads();
    }
    if (tid == 0) g_off[N_NODES] = carry;
}

__global__ void scatter_kernel(const int* __restrict__ src, const int* __restrict__ dst) {
    int e = blockIdx.x * blockDim.x + threadIdx.x;
    if (e < N_EDGES) {
        int d = dst[e];
        int p = atomicAdd(&g_cur[d], 1);
        g_psrc[g_off[d] + p] = src[e];
    }
}

// ---------------- weight packing: [F,256]x4 -> [F,1024] ----------------
__global__ void pack_kernel(const float* __restrict__ Wq, const float* __restrict__ Wk,
                            const float* __restrict__ Wv, const float* __restrict__ Ws,
                            const float* __restrict__ bq, const float* __restrict__ bk,
                            const float* __restrict__ bv, const float* __restrict__ bs,
                            int F) {
    int idx = blockIdx.x * blockDim.x + threadIdx.x;
    int total = F * 1024;
    if (idx < total) {
        int f = idx >> 10;
        int j = idx & 1023;
        int sel = j >> 8;
        int c = j & 255;
        const float* W = (sel == 0) ? Wq : (sel == 1) ? Wk : (sel == 2) ? Wv : Ws;
        g_Wc[idx] = W[f * 256 + c];
    }
    if (idx < 1024) {
        int sel = idx >> 8, c = idx & 255;
        const float* b = (sel == 0) ? bq : (sel == 1) ? bk : (sel == 2) ? bv : bs;
        g_bc[idx] = b[c];
    }
}

// ---------------- fused QKVS GEMM: C[M,1024] = A[M,K] @ Wc[K,1024] + bc ----------------
#define BM 64
#define BN 64
#define BK 16
__global__ __launch_bounds__(256) void gemm_kernel(const float* __restrict__ A, int M, int K) {
    __shared__ float As[BK][BM];
    __shared__ float Bs[BK][BN];
    int tid = threadIdx.x;
    int tx = tid & 15, ty = tid >> 4;
    int mBase = blockIdx.y * BM, nBase = blockIdx.x * BN;

    float acc[4][4] = {};
    int aRow = tid >> 2;           // 0..63
    int aCol = (tid & 3) * 4;      // 0,4,8,12
    int bRow = tid >> 4;           // 0..15
    int bCol = (tid & 15) * 4;     // 0..60

    for (int k0 = 0; k0 < K; k0 += BK) {
        float4 av = make_float4(0.f, 0.f, 0.f, 0.f);
        int gm = mBase + aRow;
        if (gm < M) av = *(const float4*)(A + (size_t)gm * K + k0 + aCol);
        As[aCol + 0][aRow] = av.x;
        As[aCol + 1][aRow] = av.y;
        As[aCol + 2][aRow] = av.z;
        As[aCol + 3][aRow] = av.w;
        float4 bv = *(const float4*)(g_Wc + (size_t)(k0 + bRow) * 1024 + nBase + bCol);
        *(float4*)&Bs[bRow][bCol] = bv;
        __syncthreads();
        #pragma unroll
        for (int kk = 0; kk < BK; kk++) {
            float4 a = *(const float4*)&As[kk][ty * 4];
            float4 b = *(const float4*)&Bs[kk][tx * 4];
            acc[0][0] += a.x * b.x; acc[0][1] += a.x * b.y; acc[0][2] += a.x * b.z; acc[0][3] += a.x * b.w;
            acc[1][0] += a.y * b.x; acc[1][1] += a.y * b.y; acc[1][2] += a.y * b.z; acc[1][3] += a.y * b.w;
            acc[2][0] += a.z * b.x; acc[2][1] += a.z * b.y; acc[2][2] += a.z * b.z; acc[2][3] += a.z * b.w;
            acc[3][0] += a.w * b.x; acc[3][1] += a.w * b.y; acc[3][2] += a.w * b.z; acc[3][3] += a.w * b.w;
        }
        __syncthreads();
    }
    int gn = nBase + tx * 4;
    float4 bias = *(const float4*)(g_bc + gn);
    #pragma unroll
    for (int i = 0; i < 4; i++) {
        int gm = mBase + ty * 4 + i;
        if (gm < M) {
            float4 o;
            o.x = acc[i][0] + bias.x;
            o.y = acc[i][1] + bias.y;
            o.z = acc[i][2] + bias.z;
            o.w = acc[i][3] + bias.w;
            *(float4*)(g_qkvs + (size_t)gm * 1024 + gn) = o;
        }
    }
}

// ---------------- attention: one warp per dst node, online softmax over CSR ----------------
__global__ __launch_bounds__(256) void attn_kernel() {
    int warp = (blockIdx.x * blockDim.x + threadIdx.x) >> 5;
    int lane = threadIdx.x & 31;
    if (warp >= N_NODES) return;

    const float* base_q = g_qkvs + (size_t)warp * 1024 + lane * 8;
    float4 q0 = *(const float4*)(base_q);
    float4 q1 = *(const float4*)(base_q + 4);

    float m = -INFINITY, s = 0.f;
    float4 a0 = make_float4(0.f, 0.f, 0.f, 0.f);
    float4 a1 = make_float4(0.f, 0.f, 0.f, 0.f);

    int e0 = g_off[warp], e1 = g_off[warp + 1];
    for (int i = e0; i < e1; i++) {
        int src = g_psrc[i];
        const float* kb = g_qkvs + (size_t)src * 1024 + 256 + lane * 8;
        float4 k0 = *(const float4*)(kb);
        float4 k1 = *(const float4*)(kb + 4);
        const float* vb = g_qkvs + (size_t)src * 1024 + 512 + lane * 8;
        float4 v0 = *(const float4*)(vb);
        float4 v1 = *(const float4*)(vb + 4);

        float d = q0.x * k0.x + q0.y * k0.y + q0.z * k0.z + q0.w * k0.w
                + q1.x * k1.x + q1.y * k1.y + q1.z * k1.z + q1.w * k1.w;
        d += __shfl_xor_sync(0xFFFFFFFFu, d, 1);
        d += __shfl_xor_sync(0xFFFFFFFFu, d, 2);
        float logit = d * 0.17677669529663687f;   // 1/sqrt(32)

        if (logit > m) {
            float sc = expf(m - logit);
            s *= sc;
            a0.x *= sc; a0.y *= sc; a0.z *= sc; a0.w *= sc;
            a1.x *= sc; a1.y *= sc; a1.z *= sc; a1.w *= sc;
            m = logit;
        }
        float p = expf(logit - m);
        s += p;
        a0.x += p * v0.x; a0.y += p * v0.y; a0.z += p * v0.z; a0.w += p * v0.w;
        a1.x += p * v1.x; a1.y += p * v1.y; a1.z += p * v1.z; a1.w += p * v1.w;
    }

    float inv = 1.f / (s + 1e-16f);
    const float* sb = g_qkvs + (size_t)warp * 1024 + 768 + lane * 8;
    float4 s0 = *(const float4*)(sb);
    float4 s1 = *(const float4*)(sb + 4);
    float4 o0, o1;
    o0.x = fmaxf(a0.x * inv + s0.x, 0.f);
    o0.y = fmaxf(a0.y * inv + s0.y, 0.f);
    o0.z = fmaxf(a0.z * inv + s0.z, 0.f);
    o0.w = fmaxf(a0.w * inv + s0.w, 0.f);
    o1.x = fmaxf(a1.x * inv + s1.x, 0.f);
    o1.y = fmaxf(a1.y * inv + s1.y, 0.f);
    o1.z = fmaxf(a1.z * inv + s1.z, 0.f);
    o1.w = fmaxf(a1.w * inv + s1.w, 0.f);
    float* hb = g_h + (size_t)warp * 256 + lane * 8;
    *(float4*)(hb) = o0;
    *(float4*)(hb + 4) = o1;
}

// ---------------- pooling ----------------
__global__ void zero_pool_kernel() {
    int i = blockIdx.x * blockDim.x + threadIdx.x;
    if (i < G_GRAPHS * HC) g_pool[i] = 0.f;
    if (i < G_GRAPHS) g_gcnt[i] = 0;
}

__global__ __launch_bounds__(256) void pool_kernel(const int* __restrict__ batch) {
    int c = threadIdx.x;  // channel 0..255
    int per = (N_NODES + gridDim.x - 1) / gridDim.x;
    int start = blockIdx.x * per;
    int end = min(N_NODES, start + per);
    if (start >= end) return;
    int cur = batch[start];
    float acc = 0.f;
    int cnt = 0;
    for (int i = start; i < end; i++) {
        int b = batch[i];
        if (b != cur) {
            atomicAdd(&g_pool[cur * HC + c], acc);
            if (c == 0) atomicAdd(&g_gcnt[cur], cnt);
            acc = 0.f; cnt = 0; cur = b;
        }
        acc += g_h[(size_t)i * HC + c];
        cnt++;
    }
    atomicAdd(&g_pool[cur * HC + c], acc);
    if (c == 0) atomicAdd(&g_gcnt[cur], cnt);
}

__global__ void fc_kernel(const float* __restrict__ Wfc, const float* __restrict__ bfc,
                          float* __restrict__ out) {
    int g = blockIdx.x;      // 0..63
    int o = threadIdx.x;     // 0..63
    __shared__ float p[HC];
    float inv = 1.f / fmaxf((float)g_gcnt[g], 1.f);
    for (int i = o; i < HC; i += OUT_F) p[i] = g_pool[g * HC + i] * inv;
    __syncthreads();
    float acc = bfc[o];
    #pragma unroll 8
    for (int f = 0; f < HC; f++) acc += p[f] * Wfc[f * OUT_F + o];
    out[g * OUT_F + o] = acc;
}

// ---------------- launch ----------------
extern "C" void kernel_launch(void* const* d_in, const int* in_sizes, int n_in,
                              void* d_out, int out_size) {
    const float* x    = (const float*)d_in[0];
    const int*   ei   = (const int*)d_in[1];
    const int*   src  = ei;
    const int*   dst  = ei + N_EDGES;
    const int*   batch = (const int*)d_in[2];
    const float* Wq0 = (const float*)d_in[3];
    const float* bq0 = (const float*)d_in[4];
    const float* Wk0 = (const float*)d_in[5];
    const float* bk0 = (const float*)d_in[6];
    const float* Wv0 = (const float*)d_in[7];
    const float* bv0 = (const float*)d_in[8];
    const float* Ws0 = (const float*)d_in[9];
    const float* bs0 = (const float*)d_in[10];
    const float* Wq  = (const float*)d_in[11];
    const float* bq  = (const float*)d_in[12];
    const float* Wk  = (const float*)d_in[13];
    const float* bk  = (const float*)d_in[14];
    const float* Wv  = (const float*)d_in[15];
    const float* bv  = (const float*)d_in[16];
    const float* Ws  = (const float*)d_in[17];
    const float* bs  = (const float*)d_in[18];
    const float* Wfc = (const float*)d_in[19];
    const float* bfc = (const float*)d_in[20];
    float* out = (float*)d_out;

    const int TB = 256;
    // CSR build (dst-sorted adjacency)
    zero_csr_kernel<<<(N_NODES + TB - 1) / TB, TB>>>();
    hist_kernel<<<(N_EDGES + TB - 1) / TB, TB>>>(dst);
    scan_kernel<<<1, 1024>>>();
    scatter_kernel<<<(N_EDGES + TB - 1) / TB, TB>>>(src, dst);

    dim3 ggrid(1024 / BN, (N_NODES + BM - 1) / BM);
    int attnBlocks = (N_NODES + 7) / 8;

    // layer 0 (IN_F -> HC)
    pack_kernel<<<(IN_F * 1024 + TB - 1) / TB, TB>>>(Wq0, Wk0, Wv0, Ws0, bq0, bk0, bv0, bs0, IN_F);
    gemm_kernel<<<ggrid, 256>>>(x, N_NODES, IN_F);
    attn_kernel<<<attnBlocks, 256>>>();

    // layers 1..3 (HC -> HC)
    float* hptr = nullptr;
    cudaGetSymbolAddress((void**)&hptr, g_h);
    for (int l = 0; l < NLAYERS - 1; l++) {
        const float* wq = Wq + (size_t)l * HC * HC;
        const float* wk = Wk + (size_t)l * HC * HC;
        const float* wv = Wv + (size_t)l * HC * HC;
        const float* ws = Ws + (size_t)l * HC * HC;
        pack_kernel<<<(HC * 1024 + TB - 1) / TB, TB>>>(wq, wk, wv, ws,
                                                       bq + l * HC, bk + l * HC,
                                                       bv + l * HC, bs + l * HC, HC);
        gemm_kernel<<<ggrid, 256>>>(hptr, N_NODES, HC);
        attn_kernel<<<attnBlocks, 256>>>();
    }

    // pooling + fc
    zero_pool_kernel<<<(G_GRAPHS * HC + TB - 1) / TB, TB>>>();
    pool_kernel<<<256, 256>>>(batch);
    fc_kernel<<<G_GRAPHS, OUT_F>>>(Wfc, bfc, out);
}

// round 3
// speedup vs baseline: 1.8640x; 1.8640x over previous
#include <cuda_runtime.h>
#include <math.h>

#define N_NODES 50000
#define N_EDGES 800000
#define IN_F    128
#define HC      256
#define G_GRAPHS 64
#define OUT_F   64
#define NLAYERS 4

// ---------------- scratch (static device allocations; no cudaMalloc) ----------------
__device__ float g_qkvs[(size_t)N_NODES * 1024];   // [q|k|v|s] per node
__device__ float g_h[(size_t)N_NODES * HC];        // layer activations
__device__ float g_Wc[256 * 1024];                 // packed [F,1024] weights for current layer
__device__ float g_bc[1024];
__device__ int   g_cnt[N_NODES];
__device__ int   g_cur[N_NODES];
__device__ int   g_off[N_NODES + 1];
__device__ int   g_psrc[N_EDGES];
__device__ float g_pool[G_GRAPHS * HC];
__device__ int   g_gcnt[G_GRAPHS];

// ---------------- CSR build ----------------
__global__ void zero_csr_kernel() {
    int i = blockIdx.x * blockDim.x + threadIdx.x;
    if (i < N_NODES) { g_cnt[i] = 0; g_cur[i] = 0; }
}

__global__ void hist_kernel(const int* __restrict__ dst) {
    int e = blockIdx.x * blockDim.x + threadIdx.x;
    if (e < N_EDGES) atomicAdd(&g_cnt[dst[e]], 1);
}

__global__ void scan_kernel() {
    __shared__ int buf[1024];
    __shared__ int carry;
    int tid = threadIdx.x;
    if (tid == 0) carry = 0;
    __syncthreads();
    for (int base = 0; base < N_NODES; base += 1024) {
        int i = base + tid;
        int v = (i < N_NODES) ? g_cnt[i] : 0;
        buf[tid] = v;
        __syncthreads();
        #pragma unroll
        for (int ofs = 1; ofs < 1024; ofs <<= 1) {
            int t = (tid >= ofs) ? buf[tid - ofs] : 0;
            __syncthreads();
            buf[tid] += t;
            __syncthreads();
        }
        int excl = buf[tid] - v + carry;
        if (i < N_NODES) g_off[i] = excl;
        __syncthreads();
        if (tid == 1023) carry += buf[1023];
        __syncthreads();
    }
    if (tid == 0) g_off[N_NODES] = carry;
}

__global__ void scatter_kernel(const int* __restrict__ src, const int* __restrict__ dst) {
    int e = blockIdx.x * blockDim.x + threadIdx.x;
    if (e < N_EDGES) {
        int d = dst[e];
        int p = atomicAdd(&g_cur[d], 1);
        g_psrc[g_off[d] + p] = src[e];
    }
}

// ---------------- weight packing: [F,256]x4 -> [F,1024] ----------------
__global__ void pack_kernel(const float* __restrict__ Wq, const float* __restrict__ Wk,
                            const float* __restrict__ Wv, const float* __restrict__ Ws,
                            const float* __restrict__ bq, const float* __restrict__ bk,
                            const float* __restrict__ bv, const float* __restrict__ bs,
                            int F) {
    int idx = blockIdx.x * blockDim.x + threadIdx.x;
    int total = F * 1024;
    if (idx < total) {
        int f = idx >> 10;
        int j = idx & 1023;
        int sel = j >> 8;
        int c = j & 255;
        const float* W = (sel == 0) ? Wq : (sel == 1) ? Wk : (sel == 2) ? Wv : Ws;
        g_Wc[idx] = W[f * 256 + c];
    }
    if (idx < 1024) {
        int sel = idx >> 8, c = idx & 255;
        const float* b = (sel == 0) ? bq : (sel == 1) ? bk : (sel == 2) ? bv : bs;
        g_bc[idx] = b[c];
    }
}

// ---------------- TF32 tensor-core GEMM: C[M,1024] = A[M,K] @ Wc[K,1024] + bc ----------------
// Block tile 128x128, BK=16, 8 warps (2 along M x 4 along N), warp tile 64x32.
// mma.sync.aligned.m16n8k8.row.col.f32.tf32.tf32.f32
#define GBM 128
#define GBN 128
#define GBK 16
#define APITCH 20    // pad: 20*4=80B row, 16B aligned, conflict-free
#define BPITCH 132   // pad: 132*4=528B row, 16B aligned, conflict-free

__device__ __forceinline__ unsigned f2tf32(float f) {
    unsigned r;
    asm("cvt.rna.tf32.f32 %0, %1;" : "=r"(r) : "f"(f));
    return r;
}

__global__ __launch_bounds__(256) void gemm_tc_kernel(const float* __restrict__ A, int M, int K) {
    __shared__ unsigned As[GBM * APITCH];
    __shared__ unsigned Bs[GBK * BPITCH];

    int tid  = threadIdx.x;
    int lane = tid & 31;
    int wid  = tid >> 5;
    int gid  = lane >> 2;   // 0..7
    int tig  = lane & 3;    // 0..3
    int warpM = wid & 1;    // 0..1  (64 rows each)
    int warpN = wid >> 1;   // 0..3  (32 cols each)

    int mBase = blockIdx.y * GBM;
    int nBase = blockIdx.x * GBN;

    float c[4][4][4];       // [mt][nt][reg]
    #pragma unroll
    for (int i = 0; i < 4; i++)
        #pragma unroll
        for (int j = 0; j < 4; j++)
            #pragma unroll
            for (int r = 0; r < 4; r++) c[i][j][r] = 0.f;

    for (int k0 = 0; k0 < K; k0 += GBK) {
        // load A tile: 128 rows x 16 cols = 512 float4; 2 per thread
        #pragma unroll
        for (int t = 0; t < 2; t++) {
            int idx = tid * 2 + t;              // 0..511
            int row = idx >> 2;                 // 0..127
            int c4  = idx & 3;                  // 0..3
            float4 av = make_float4(0.f, 0.f, 0.f, 0.f);
            int gm = mBase + row;
            if (gm < M) av = *(const float4*)(A + (size_t)gm * K + k0 + c4 * 4);
            uint4 tv;
            tv.x = f2tf32(av.x); tv.y = f2tf32(av.y);
            tv.z = f2tf32(av.z); tv.w = f2tf32(av.w);
            *(uint4*)&As[row * APITCH + c4 * 4] = tv;
        }
        // load B tile: 16 rows x 128 cols = 512 float4; 2 per thread
        #pragma unroll
        for (int t = 0; t < 2; t++) {
            int idx = tid * 2 + t;              // 0..511
            int row = idx >> 5;                 // 0..15
            int c4  = idx & 31;                 // 0..31
            float4 bv = *(const float4*)(g_Wc + (size_t)(k0 + row) * 1024 + nBase + c4 * 4);
            uint4 tv;
            tv.x = f2tf32(bv.x); tv.y = f2tf32(bv.y);
            tv.z = f2tf32(bv.z); tv.w = f2tf32(bv.w);
            *(uint4*)&Bs[row * BPITCH + c4 * 4] = tv;
        }
        __syncthreads();

        #pragma unroll
        for (int ks = 0; ks < 2; ks++) {
            int kk = ks * 8;
            // A fragments: 4 m-tiles
            unsigned af[4][4];
            #pragma unroll
            for (int mt = 0; mt < 4; mt++) {
                int r0 = warpM * 64 + mt * 16 + gid;
                af[mt][0] = As[(r0    ) * APITCH + kk + tig];
                af[mt][1] = As[(r0 + 8) * APITCH + kk + tig];
                af[mt][2] = As[(r0    ) * APITCH + kk + tig + 4];
                af[mt][3] = As[(r0 + 8) * APITCH + kk + tig + 4];
            }
            // B fragments: 4 n-tiles
            unsigned bf[4][2];
            #pragma unroll
            for (int nt = 0; nt < 4; nt++) {
                int col = warpN * 32 + nt * 8 + gid;
                bf[nt][0] = Bs[(kk + tig    ) * BPITCH + col];
                bf[nt][1] = Bs[(kk + tig + 4) * BPITCH + col];
            }
            #pragma unroll
            for (int mt = 0; mt < 4; mt++)
                #pragma unroll
                for (int nt = 0; nt < 4; nt++) {
                    asm volatile(
                        "mma.sync.aligned.m16n8k8.row.col.f32.tf32.tf32.f32 "
                        "{%0,%1,%2,%3}, {%4,%5,%6,%7}, {%8,%9}, {%0,%1,%2,%3};"
                        : "+f"(c[mt][nt][0]), "+f"(c[mt][nt][1]),
                          "+f"(c[mt][nt][2]), "+f"(c[mt][nt][3])
                        : "r"(af[mt][0]), "r"(af[mt][1]), "r"(af[mt][2]), "r"(af[mt][3]),
                          "r"(bf[nt][0]), "r"(bf[nt][1]));
                }
        }
        __syncthreads();
    }

    // epilogue: bias + store
    #pragma unroll
    for (int nt = 0; nt < 4; nt++) {
        int col = nBase + warpN * 32 + nt * 8 + tig * 2;
        float2 bias = *(const float2*)(g_bc + col);
        #pragma unroll
        for (int mt = 0; mt < 4; mt++) {
            int row0 = mBase + warpM * 64 + mt * 16 + gid;
            if (row0 < M) {
                float2 o;
                o.x = c[mt][nt][0] + bias.x;
                o.y = c[mt][nt][1] + bias.y;
                *(float2*)(g_qkvs + (size_t)row0 * 1024 + col) = o;
            }
            int row1 = row0 + 8;
            if (row1 < M) {
                float2 o;
                o.x = c[mt][nt][2] + bias.x;
                o.y = c[mt][nt][3] + bias.y;
                *(float2*)(g_qkvs + (size_t)row1 * 1024 + col) = o;
            }
        }
    }
}

// ---------------- attention: one warp per dst node, online softmax over CSR ----------------
__global__ __launch_bounds__(256) void attn_kernel() {
    int warp = (blockIdx.x * blockDim.x + threadIdx.x) >> 5;
    int lane = threadIdx.x & 31;
    if (warp >= N_NODES) return;

    const float* base_q = g_qkvs + (size_t)warp * 1024 + lane * 8;
    float4 q0 = *(const float4*)(base_q);
    float4 q1 = *(const float4*)(base_q + 4);

    float m = -INFINITY, s = 0.f;
    float4 a0 = make_float4(0.f, 0.f, 0.f, 0.f);
    float4 a1 = make_float4(0.f, 0.f, 0.f, 0.f);

    int e0 = g_off[warp], e1 = g_off[warp + 1];
    for (int i = e0; i < e1; i++) {
        int src = g_psrc[i];
        const float* kb = g_qkvs + (size_t)src * 1024 + 256 + lane * 8;
        float4 k0 = *(const float4*)(kb);
        float4 k1 = *(const float4*)(kb + 4);
        const float* vb = g_qkvs + (size_t)src * 1024 + 512 + lane * 8;
        float4 v0 = *(const float4*)(vb);
        float4 v1 = *(const float4*)(vb + 4);

        float d = q0.x * k0.x + q0.y * k0.y + q0.z * k0.z + q0.w * k0.w
                + q1.x * k1.x + q1.y * k1.y + q1.z * k1.z + q1.w * k1.w;
        d += __shfl_xor_sync(0xFFFFFFFFu, d, 1);
        d += __shfl_xor_sync(0xFFFFFFFFu, d, 2);
        float logit = d * 0.17677669529663687f;   // 1/sqrt(32)

        if (logit > m) {
            float sc = expf(m - logit);
            s *= sc;
            a0.x *= sc; a0.y *= sc; a0.z *= sc; a0.w *= sc;
            a1.x *= sc; a1.y *= sc; a1.z *= sc; a1.w *= sc;
            m = logit;
        }
        float p = expf(logit - m);
        s += p;
        a0.x += p * v0.x; a0.y += p * v0.y; a0.z += p * v0.z; a0.w += p * v0.w;
        a1.x += p * v1.x; a1.y += p * v1.y; a1.z += p * v1.z; a1.w += p * v1.w;
    }

    float inv = 1.f / (s + 1e-16f);
    const float* sb = g_qkvs + (size_t)warp * 1024 + 768 + lane * 8;
    float4 s0 = *(const float4*)(sb);
    float4 s1 = *(const float4*)(sb + 4);
    float4 o0, o1;
    o0.x = fmaxf(a0.x * inv + s0.x, 0.f);
    o0.y = fmaxf(a0.y * inv + s0.y, 0.f);
    o0.z = fmaxf(a0.z * inv + s0.z, 0.f);
    o0.w = fmaxf(a0.w * inv + s0.w, 0.f);
    o1.x = fmaxf(a1.x * inv + s1.x, 0.f);
    o1.y = fmaxf(a1.y * inv + s1.y, 0.f);
    o1.z = fmaxf(a1.z * inv + s1.z, 0.f);
    o1.w = fmaxf(a1.w * inv + s1.w, 0.f);
    float* hb = g_h + (size_t)warp * 256 + lane * 8;
    *(float4*)(hb) = o0;
    *(float4*)(hb + 4) = o1;
}

// ---------------- pooling ----------------
__global__ void zero_pool_kernel() {
    int i = blockIdx.x * blockDim.x + threadIdx.x;
    if (i < G_GRAPHS * HC) g_pool[i] = 0.f;
    if (i < G_GRAPHS) g_gcnt[i] = 0;
}

__global__ __launch_bounds__(256) void pool_kernel(const int* __restrict__ batch) {
    int c = threadIdx.x;  // channel 0..255
    int per = (N_NODES + gridDim.x - 1) / gridDim.x;
    int start = blockIdx.x * per;
    int end = min(N_NODES, start + per);
    if (start >= end) return;
    int cur = batch[start];
    float acc = 0.f;
    int cnt = 0;
    for (int i = start; i < end; i++) {
        int b = batch[i];
        if (b != cur) {
            atomicAdd(&g_pool[cur * HC + c], acc);
            if (c == 0) atomicAdd(&g_gcnt[cur], cnt);
            acc = 0.f; cnt = 0; cur = b;
        }
        acc += g_h[(size_t)i * HC + c];
        cnt++;
    }
    atomicAdd(&g_pool[cur * HC + c], acc);
    if (c == 0) atomicAdd(&g_gcnt[cur], cnt);
}

__global__ void fc_kernel(const float* __restrict__ Wfc, const float* __restrict__ bfc,
                          float* __restrict__ out) {
    int g = blockIdx.x;      // 0..63
    int o = threadIdx.x;     // 0..63
    __shared__ float p[HC];
    float inv = 1.f / fmaxf((float)g_gcnt[g], 1.f);
    for (int i = o; i < HC; i += OUT_F) p[i] = g_pool[g * HC + i] * inv;
    __syncthreads();
    float acc = bfc[o];
    #pragma unroll 8
    for (int f = 0; f < HC; f++) acc += p[f] * Wfc[f * OUT_F + o];
    out[g * OUT_F + o] = acc;
}

// ---------------- launch ----------------
extern "C" void kernel_launch(void* const* d_in, const int* in_sizes, int n_in,
                              void* d_out, int out_size) {
    const float* x    = (const float*)d_in[0];
    const int*   ei   = (const int*)d_in[1];
    const int*   src  = ei;
    const int*   dst  = ei + N_EDGES;
    const int*   batch = (const int*)d_in[2];
    const float* Wq0 = (const float*)d_in[3];
    const float* bq0 = (const float*)d_in[4];
    const float* Wk0 = (const float*)d_in[5];
    const float* bk0 = (const float*)d_in[6];
    const float* Wv0 = (const float*)d_in[7];
    const float* bv0 = (const float*)d_in[8];
    const float* Ws0 = (const float*)d_in[9];
    const float* bs0 = (const float*)d_in[10];
    const float* Wq  = (const float*)d_in[11];
    const float* bq  = (const float*)d_in[12];
    const float* Wk  = (const float*)d_in[13];
    const float* bk  = (const float*)d_in[14];
    const float* Wv  = (const float*)d_in[15];
    const float* bv  = (const float*)d_in[16];
    const float* Ws  = (const float*)d_in[17];
    const float* bs  = (const float*)d_in[18];
    const float* Wfc = (const float*)d_in[19];
    const float* bfc = (const float*)d_in[20];
    float* out = (float*)d_out;

    const int TB = 256;
    // CSR build (dst-sorted adjacency)
    zero_csr_kernel<<<(N_NODES + TB - 1) / TB, TB>>>();
    hist_kernel<<<(N_EDGES + TB - 1) / TB, TB>>>(dst);
    scan_kernel<<<1, 1024>>>();
    scatter_kernel<<<(N_EDGES + TB - 1) / TB, TB>>>(src, dst);

    dim3 ggrid(1024 / GBN, (N_NODES + GBM - 1) / GBM);
    int attnBlocks = (N_NODES + 7) / 8;

    // layer 0 (IN_F -> HC)
    pack_kernel<<<(IN_F * 1024 + TB - 1) / TB, TB>>>(Wq0, Wk0, Wv0, Ws0, bq0, bk0, bv0, bs0, IN_F);
    gemm_tc_kernel<<<ggrid, 256>>>(x, N_NODES, IN_F);
    attn_kernel<<<attnBlocks, 256>>>();

    // layers 1..3 (HC -> HC)
    float* hptr = nullptr;
    cudaGetSymbolAddress((void**)&hptr, g_h);
    for (int l = 0; l < NLAYERS - 1; l++) {
        const float* wq = Wq + (size_t)l * HC * HC;
        const float* wk = Wk + (size_t)l * HC * HC;
        const float* wv = Wv + (size_t)l * HC * HC;
        const float* ws = Ws + (size_t)l * HC * HC;
        pack_kernel<<<(HC * 1024 + TB - 1) / TB, TB>>>(wq, wk, wv, ws,
                                                       bq + l * HC, bk + l * HC,
                                                       bv + l * HC, bs + l * HC, HC);
        gemm_tc_kernel<<<ggrid, 256>>>(hptr, N_NODES, HC);
        attn_kernel<<<attnBlocks, 256>>>();
    }

    // pooling + fc
    zero_pool_kernel<<<(G_GRAPHS * HC + TB - 1) / TB, TB>>>();
    pool_kernel<<<256, 256>>>(batch);
    fc_kernel<<<G_GRAPHS, OUT_F>>>(Wfc, bfc, out);
}

// round 4
// speedup vs baseline: 2.0981x; 1.1256x over previous
#include <cuda_runtime.h>
#include <cuda_fp16.h>
#include <math.h>

#define N_NODES 50000
#define N_EDGES 800000
#define IN_F    128
#define HC      256
#define G_GRAPHS 64
#define OUT_F   64
#define NLAYERS 4

// ---------------- scratch (static device allocations; no cudaMalloc) ----------------
__device__ float  g_qs[(size_t)N_NODES * 512];    // [q|s] per node, fp32 (102.4 MB)
__device__ __half g_kv[(size_t)N_NODES * 512];    // [k|v] per node, fp16 (51.2 MB)
__device__ float  g_h[(size_t)N_NODES * HC];      // layer activations
__device__ float  g_Wc[256 * 1024];               // packed [F,1024] weights for current layer
__device__ float  g_bc[1024];
__device__ int    g_cnt[N_NODES];
__device__ int    g_cur[N_NODES];
__device__ int    g_off[N_NODES + 1];
__device__ int    g_psrc[N_EDGES];
__device__ float  g_pool[G_GRAPHS * HC];
__device__ int    g_gcnt[G_GRAPHS];

// ---------------- CSR build ----------------
__global__ void zero_csr_kernel() {
    int i = blockIdx.x * blockDim.x + threadIdx.x;
    if (i < N_NODES) { g_cnt[i] = 0; g_cur[i] = 0; }
}

__global__ void hist_kernel(const int* __restrict__ dst) {
    int e = blockIdx.x * blockDim.x + threadIdx.x;
    if (e < N_EDGES) atomicAdd(&g_cnt[dst[e]], 1);
}

__global__ void scan_kernel() {
    __shared__ int buf[1024];
    __shared__ int carry;
    int tid = threadIdx.x;
    if (tid == 0) carry = 0;
    __syncthreads();
    for (int base = 0; base < N_NODES; base += 1024) {
        int i = base + tid;
        int v = (i < N_NODES) ? g_cnt[i] : 0;
        buf[tid] = v;
        __syncthreads();
        #pragma unroll
        for (int ofs = 1; ofs < 1024; ofs <<= 1) {
            int t = (tid >= ofs) ? buf[tid - ofs] : 0;
            __syncthreads();
            buf[tid] += t;
            __syncthreads();
        }
        int excl = buf[tid] - v + carry;
        if (i < N_NODES) g_off[i] = excl;
        __syncthreads();
        if (tid == 1023) carry += buf[1023];
        __syncthreads();
    }
    if (tid == 0) g_off[N_NODES] = carry;
}

__global__ void scatter_kernel(const int* __restrict__ src, const int* __restrict__ dst) {
    int e = blockIdx.x * blockDim.x + threadIdx.x;
    if (e < N_EDGES) {
        int d = dst[e];
        int p = atomicAdd(&g_cur[d], 1);
        g_psrc[g_off[d] + p] = src[e];
    }
}

// ---------------- weight packing: [F,256]x4 -> [F,1024] ----------------
__global__ void pack_kernel(const float* __restrict__ Wq, const float* __restrict__ Wk,
                            const float* __restrict__ Wv, const float* __restrict__ Ws,
                            const float* __restrict__ bq, const float* __restrict__ bk,
                            const float* __restrict__ bv, const float* __restrict__ bs,
                            int F) {
    int idx = blockIdx.x * blockDim.x + threadIdx.x;
    int total = F * 1024;
    if (idx < total) {
        int f = idx >> 10;
        int j = idx & 1023;
        int sel = j >> 8;
        int c = j & 255;
        const float* W = (sel == 0) ? Wq : (sel == 1) ? Wk : (sel == 2) ? Wv : Ws;
        g_Wc[idx] = W[f * 256 + c];
    }
    if (idx < 1024) {
        int sel = idx >> 8, c = idx & 255;
        const float* b = (sel == 0) ? bq : (sel == 1) ? bk : (sel == 2) ? bv : bs;
        g_bc[idx] = b[c];
    }
}

// ---------------- TF32 tensor-core GEMM: [M,K] @ Wc[K,1024] + bc ----------------
// Output routed by column: q(0-255)->g_qs fp32, k/v(256-767)->g_kv fp16, s(768-1023)->g_qs fp32.
#define GBM 128
#define GBN 128
#define GBK 16
#define APITCH 20
#define BPITCH 132

__device__ __forceinline__ unsigned f2tf32(float f) {
    unsigned r;
    asm("cvt.rna.tf32.f32 %0, %1;" : "=r"(r) : "f"(f));
    return r;
}

__device__ __forceinline__ void store_seg(int row, int col, float vx, float vy) {
    if (col < 256) {
        float2 o = make_float2(vx, vy);
        *(float2*)(g_qs + (size_t)row * 512 + col) = o;
    } else if (col < 768) {
        *(__half2*)(g_kv + (size_t)row * 512 + (col - 256)) = __floats2half2_rn(vx, vy);
    } else {
        float2 o = make_float2(vx, vy);
        *(float2*)(g_qs + (size_t)row * 512 + 256 + (col - 768)) = o;
    }
}

__global__ __launch_bounds__(256) void gemm_tc_kernel(const float* __restrict__ A, int M, int K) {
    __shared__ unsigned As[GBM * APITCH];
    __shared__ unsigned Bs[GBK * BPITCH];

    int tid  = threadIdx.x;
    int lane = tid & 31;
    int wid  = tid >> 5;
    int gid  = lane >> 2;
    int tig  = lane & 3;
    int warpM = wid & 1;
    int warpN = wid >> 1;

    int mBase = blockIdx.y * GBM;
    int nBase = blockIdx.x * GBN;

    float c[4][4][4];
    #pragma unroll
    for (int i = 0; i < 4; i++)
        #pragma unroll
        for (int j = 0; j < 4; j++)
            #pragma unroll
            for (int r = 0; r < 4; r++) c[i][j][r] = 0.f;

    for (int k0 = 0; k0 < K; k0 += GBK) {
        #pragma unroll
        for (int t = 0; t < 2; t++) {
            int idx = tid * 2 + t;
            int row = idx >> 2;
            int c4  = idx & 3;
            float4 av = make_float4(0.f, 0.f, 0.f, 0.f);
            int gm = mBase + row;
            if (gm < M) av = *(const float4*)(A + (size_t)gm * K + k0 + c4 * 4);
            uint4 tv;
            tv.x = f2tf32(av.x); tv.y = f2tf32(av.y);
            tv.z = f2tf32(av.z); tv.w = f2tf32(av.w);
            *(uint4*)&As[row * APITCH + c4 * 4] = tv;
        }
        #pragma unroll
        for (int t = 0; t < 2; t++) {
            int idx = tid * 2 + t;
            int row = idx >> 5;
            int c4  = idx & 31;
            float4 bv = *(const float4*)(g_Wc + (size_t)(k0 + row) * 1024 + nBase + c4 * 4);
            uint4 tv;
            tv.x = f2tf32(bv.x); tv.y = f2tf32(bv.y);
            tv.z = f2tf32(bv.z); tv.w = f2tf32(bv.w);
            *(uint4*)&Bs[row * BPITCH + c4 * 4] = tv;
        }
        __syncthreads();

        #pragma unroll
        for (int ks = 0; ks < 2; ks++) {
            int kk = ks * 8;
            unsigned af[4][4];
            #pragma unroll
            for (int mt = 0; mt < 4; mt++) {
                int r0 = warpM * 64 + mt * 16 + gid;
                af[mt][0] = As[(r0    ) * APITCH + kk + tig];
                af[mt][1] = As[(r0 + 8) * APITCH + kk + tig];
                af[mt][2] = As[(r0    ) * APITCH + kk + tig + 4];
                af[mt][3] = As[(r0 + 8) * APITCH + kk + tig + 4];
            }
            unsigned bf[4][2];
            #pragma unroll
            for (int nt = 0; nt < 4; nt++) {
                int col = warpN * 32 + nt * 8 + gid;
                bf[nt][0] = Bs[(kk + tig    ) * BPITCH + col];
                bf[nt][1] = Bs[(kk + tig + 4) * BPITCH + col];
            }
            #pragma unroll
            for (int mt = 0; mt < 4; mt++)
                #pragma unroll
                for (int nt = 0; nt < 4; nt++) {
                    asm volatile(
                        "mma.sync.aligned.m16n8k8.row.col.f32.tf32.tf32.f32 "
                        "{%0,%1,%2,%3}, {%4,%5,%6,%7}, {%8,%9}, {%0,%1,%2,%3};"
                        : "+f"(c[mt][nt][0]), "+f"(c[mt][nt][1]),
                          "+f"(c[mt][nt][2]), "+f"(c[mt][nt][3])
                        : "r"(af[mt][0]), "r"(af[mt][1]), "r"(af[mt][2]), "r"(af[mt][3]),
                          "r"(bf[nt][0]), "r"(bf[nt][1]));
                }
        }
        __syncthreads();
    }

    // epilogue: bias + routed store
    #pragma unroll
    for (int nt = 0; nt < 4; nt++) {
        int col = nBase + warpN * 32 + nt * 8 + tig * 2;
        float2 bias = *(const float2*)(g_bc + col);
        #pragma unroll
        for (int mt = 0; mt < 4; mt++) {
            int row0 = mBase + warpM * 64 + mt * 16 + gid;
            if (row0 < M)
                store_seg(row0, col, c[mt][nt][0] + bias.x, c[mt][nt][1] + bias.y);
            int row1 = row0 + 8;
            if (row1 < M)
                store_seg(row1, col, c[mt][nt][2] + bias.x, c[mt][nt][3] + bias.y);
        }
    }
}

// ---------------- attention: one warp per dst node, online softmax, fp16 K/V gather ----------------
__global__ __launch_bounds__(256) void attn_kernel() {
    int warp = (blockIdx.x * blockDim.x + threadIdx.x) >> 5;
    int lane = threadIdx.x & 31;
    if (warp >= N_NODES) return;

    const float* base_q = g_qs + (size_t)warp * 512 + lane * 8;
    float4 q0 = *(const float4*)(base_q);
    float4 q1 = *(const float4*)(base_q + 4);

    float m = -INFINITY, s = 0.f;
    float4 a0 = make_float4(0.f, 0.f, 0.f, 0.f);
    float4 a1 = make_float4(0.f, 0.f, 0.f, 0.f);

    int e0 = g_off[warp], e1 = g_off[warp + 1];
    for (int i = e0; i < e1; i++) {
        int src = g_psrc[i];
        const __half* kvb = g_kv + (size_t)src * 512 + lane * 8;
        uint4 kraw = *(const uint4*)(kvb);          // 8 halfs of K
        uint4 vraw = *(const uint4*)(kvb + 256);    // 8 halfs of V

        float2 k01 = __half22float2(*(const __half2*)&kraw.x);
        float2 k23 = __half22float2(*(const __half2*)&kraw.y);
        float2 k45 = __half22float2(*(const __half2*)&kraw.z);
        float2 k67 = __half22float2(*(const __half2*)&kraw.w);

        float d = q0.x * k01.x + q0.y * k01.y + q0.z * k23.x + q0.w * k23.y
                + q1.x * k45.x + q1.y * k45.y + q1.z * k67.x + q1.w * k67.y;
        d += __shfl_xor_sync(0xFFFFFFFFu, d, 1);
        d += __shfl_xor_sync(0xFFFFFFFFu, d, 2);
        float logit = d * 0.17677669529663687f;   // 1/sqrt(32)

        float mN = fmaxf(m, logit);
        float sc = __expf(m - mN);                 // exp(-inf)=0 handles init
        float p  = __expf(logit - mN);
        m = mN;
        s = s * sc + p;

        float2 v01 = __half22float2(*(const __half2*)&vraw.x);
        float2 v23 = __half22float2(*(const __half2*)&vraw.y);
        float2 v45 = __half22float2(*(const __half2*)&vraw.z);
        float2 v67 = __half22float2(*(const __half2*)&vraw.w);

        a0.x = a0.x * sc + p * v01.x; a0.y = a0.y * sc + p * v01.y;
        a0.z = a0.z * sc + p * v23.x; a0.w = a0.w * sc + p * v23.y;
        a1.x = a1.x * sc + p * v45.x; a1.y = a1.y * sc + p * v45.y;
        a1.z = a1.z * sc + p * v67.x; a1.w = a1.w * sc + p * v67.y;
    }

    float inv = 1.f / (s + 1e-16f);
    const float* sb = g_qs + (size_t)warp * 512 + 256 + lane * 8;
    float4 s0 = *(const float4*)(sb);
    float4 s1 = *(const float4*)(sb + 4);
    float4 o0, o1;
    o0.x = fmaxf(a0.x * inv + s0.x, 0.f);
    o0.y = fmaxf(a0.y * inv + s0.y, 0.f);
    o0.z = fmaxf(a0.z * inv + s0.z, 0.f);
    o0.w = fmaxf(a0.w * inv + s0.w, 0.f);
    o1.x = fmaxf(a1.x * inv + s1.x, 0.f);
    o1.y = fmaxf(a1.y * inv + s1.y, 0.f);
    o1.z = fmaxf(a1.z * inv + s1.z, 0.f);
    o1.w = fmaxf(a1.w * inv + s1.w, 0.f);
    float* hb = g_h + (size_t)warp * 256 + lane * 8;
    *(float4*)(hb) = o0;
    *(float4*)(hb + 4) = o1;
}

// ---------------- pooling ----------------
__global__ void zero_pool_kernel() {
    int i = blockIdx.x * blockDim.x + threadIdx.x;
    if (i < G_GRAPHS * HC) g_pool[i] = 0.f;
    if (i < G_GRAPHS) g_gcnt[i] = 0;
}

__global__ __launch_bounds__(256) void pool_kernel(const int* __restrict__ batch) {
    int c = threadIdx.x;
    int per = (N_NODES + gridDim.x - 1) / gridDim.x;
    int start = blockIdx.x * per;
    int end = min(N_NODES, start + per);
    if (start >= end) return;
    int cur = batch[start];
    float acc = 0.f;
    int cnt = 0;
    for (int i = start; i < end; i++) {
        int b = batch[i];
        if (b != cur) {
            atomicAdd(&g_pool[cur * HC + c], acc);
            if (c == 0) atomicAdd(&g_gcnt[cur], cnt);
            acc = 0.f; cnt = 0; cur = b;
        }
        acc += g_h[(size_t)i * HC + c];
        cnt++;
    }
    atomicAdd(&g_pool[cur * HC + c], acc);
    if (c == 0) atomicAdd(&g_gcnt[cur], cnt);
}

__global__ void fc_kernel(const float* __restrict__ Wfc, const float* __restrict__ bfc,
                          float* __restrict__ out) {
    int g = blockIdx.x;
    int o = threadIdx.x;
    __shared__ float p[HC];
    float inv = 1.f / fmaxf((float)g_gcnt[g], 1.f);
    for (int i = o; i < HC; i += OUT_F) p[i] = g_pool[g * HC + i] * inv;
    __syncthreads();
    float acc = bfc[o];
    #pragma unroll 8
    for (int f = 0; f < HC; f++) acc += p[f] * Wfc[f * OUT_F + o];
    out[g * OUT_F + o] = acc;
}

// ---------------- launch ----------------
extern "C" void kernel_launch(void* const* d_in, const int* in_sizes, int n_in,
                              void* d_out, int out_size) {
    const float* x    = (const float*)d_in[0];
    const int*   ei   = (const int*)d_in[1];
    const int*   src  = ei;
    const int*   dst  = ei + N_EDGES;
    const int*   batch = (const int*)d_in[2];
    const float* Wq0 = (const float*)d_in[3];
    const float* bq0 = (const float*)d_in[4];
    const float* Wk0 = (const float*)d_in[5];
    const float* bk0 = (const float*)d_in[6];
    const float* Wv0 = (const float*)d_in[7];
    const float* bv0 = (const float*)d_in[8];
    const float* Ws0 = (const float*)d_in[9];
    const float* bs0 = (const float*)d_in[10];
    const float* Wq  = (const float*)d_in[11];
    const float* bq  = (const float*)d_in[12];
    const float* Wk  = (const float*)d_in[13];
    const float* bk  = (const float*)d_in[14];
    const float* Wv  = (const float*)d_in[15];
    const float* bv  = (const float*)d_in[16];
    const float* Ws  = (const float*)d_in[17];
    const float* bs  = (const float*)d_in[18];
    const float* Wfc = (const float*)d_in[19];
    const float* bfc = (const float*)d_in[20];
    float* out = (float*)d_out;

    const int TB = 256;
    // CSR build (dst-sorted adjacency)
    zero_csr_kernel<<<(N_NODES + TB - 1) / TB, TB>>>();
    hist_kernel<<<(N_EDGES + TB - 1) / TB, TB>>>(dst);
    scan_kernel<<<1, 1024>>>();
    scatter_kernel<<<(N_EDGES + TB - 1) / TB, TB>>>(src, dst);

    dim3 ggrid(1024 / GBN, (N_NODES + GBM - 1) / GBM);
    int attnBlocks = (N_NODES + 7) / 8;

    // layer 0 (IN_F -> HC)
    pack_kernel<<<(IN_F * 1024 + TB - 1) / TB, TB>>>(Wq0, Wk0, Wv0, Ws0, bq0, bk0, bv0, bs0, IN_F);
    gemm_tc_kernel<<<ggrid, 256>>>(x, N_NODES, IN_F);
    attn_kernel<<<attnBlocks, 256>>>();

    // layers 1..3 (HC -> HC)
    float* hptr = nullptr;
    cudaGetSymbolAddress((void**)&hptr, g_h);
    for (int l = 0; l < NLAYERS - 1; l++) {
        const float* wq = Wq + (size_t)l * HC * HC;
        const float* wk = Wk + (size_t)l * HC * HC;
        const float* wv = Wv + (size_t)l * HC * HC;
        const float* ws = Ws + (size_t)l * HC * HC;
        pack_kernel<<<(HC * 1024 + TB - 1) / TB, TB>>>(wq, wk, wv, ws,
                                                       bq + l * HC, bk + l * HC,
                                                       bv + l * HC, bs + l * HC, HC);
        gemm_tc_kernel<<<ggrid, 256>>>(hptr, N_NODES, HC);
        attn_kernel<<<attnBlocks, 256>>>();
    }

    // pooling + fc
    zero_pool_kernel<<<(G_GRAPHS * HC + TB - 1) / TB, TB>>>();
    pool_kernel<<<256, 256>>>(batch);
    fc_kernel<<<G_GRAPHS, OUT_F>>>(Wfc, bfc, out);
}

// round 8
// speedup vs baseline: 2.2048x; 1.0508x over previous
#include <cuda_runtime.h>
#include <cuda_fp16.h>
#include <math.h>

#define N_NODES 50000
#define N_EDGES 800000
#define IN_F    128
#define HC      256
#define G_GRAPHS 64
#define OUT_F   64
#define NLAYERS 4

// ---------------- scratch (static device allocations; no cudaMalloc) ----------------
__device__ float  g_qs[(size_t)N_NODES * 512];    // [q|s] per node, fp32
__device__ __half g_kv[(size_t)N_NODES * 512];    // [k|v] per node, fp16
__device__ float  g_h[(size_t)N_NODES * HC];      // layer activations
__device__ float  g_Wc[256 * 1024];               // packed [F,1024] weights, RNA-rounded to tf32
__device__ float  g_bc[1024];
__device__ int    g_cnt[N_NODES];
__device__ int    g_cur[N_NODES];
__device__ int    g_off[N_NODES + 1];
__device__ int    g_psrc[N_EDGES];
__device__ float  g_pool[G_GRAPHS * HC];
__device__ int    g_gcnt[G_GRAPHS];

__device__ __forceinline__ unsigned f2tf32(float f) {
    unsigned r;
    asm("cvt.rna.tf32.f32 %0, %1;" : "=r"(r) : "f"(f));
    return r;
}

// ---------------- CSR build ----------------
__global__ void zero_csr_kernel() {
    int i = blockIdx.x * blockDim.x + threadIdx.x;
    if (i < N_NODES) { g_cnt[i] = 0; g_cur[i] = 0; }
}

__global__ void hist_kernel(const int* __restrict__ dst) {
    int e = blockIdx.x * blockDim.x + threadIdx.x;
    if (e < N_EDGES) atomicAdd(&g_cnt[dst[e]], 1);
}

__global__ void scan_kernel() {
    __shared__ int buf[1024];
    __shared__ int carry;
    int tid = threadIdx.x;
    if (tid == 0) carry = 0;
    __syncthreads();
    for (int base = 0; base < N_NODES; base += 1024) {
        int i = base + tid;
        int v = (i < N_NODES) ? g_cnt[i] : 0;
        buf[tid] = v;
        __syncthreads();
        #pragma unroll
        for (int ofs = 1; ofs < 1024; ofs <<= 1) {
            int t = (tid >= ofs) ? buf[tid - ofs] : 0;
            __syncthreads();
            buf[tid] += t;
            __syncthreads();
        }
        int excl = buf[tid] - v + carry;
        if (i < N_NODES) g_off[i] = excl;
        __syncthreads();
        if (tid == 1023) carry += buf[1023];
        __syncthreads();
    }
    if (tid == 0) g_off[N_NODES] = carry;
}

__global__ void scatter_kernel(const int* __restrict__ src, const int* __restrict__ dst) {
    int e = blockIdx.x * blockDim.x + threadIdx.x;
    if (e < N_EDGES) {
        int d = dst[e];
        int p = atomicAdd(&g_cur[d], 1);
        g_psrc[g_off[d] + p] = src[e];
    }
}

// ---------------- weight packing: [F,256]x4 -> [F,1024], RNA-rounded to tf32 ----------------
__global__ void pack_kernel(const float* __restrict__ Wq, const float* __restrict__ Wk,
                            const float* __restrict__ Wv, const float* __restrict__ Ws,
                            const float* __restrict__ bq, const float* __restrict__ bk,
                            const float* __restrict__ bv, const float* __restrict__ bs,
                            int F) {
    int idx = blockIdx.x * blockDim.x + threadIdx.x;
    int total = F * 1024;
    if (idx < total) {
        int f = idx >> 10;
        int j = idx & 1023;
        int sel = j >> 8;
        int c = j & 255;
        const float* W = (sel == 0) ? Wq : (sel == 1) ? Wk : (sel == 2) ? Wv : Ws;
        unsigned t = f2tf32(W[f * 256 + c]);           // round-to-nearest tf32, stored as fp32 bits
        g_Wc[idx] = __uint_as_float(t);
    }
    if (idx < 1024) {
        int sel = idx >> 8, c = idx & 255;
        const float* b = (sel == 0) ? bq : (sel == 1) ? bk : (sel == 2) ? bv : bs;
        g_bc[idx] = b[c];
    }
}

// ---------------- TF32 tensor-core GEMM with cp.async double buffering ----------------
// C[M,1024] = A[M,K] @ Wc[K,1024] + bc ; output routed by column segment.
// B pre-rounded (pack_kernel); A RNA-rounded in-register on the fragments.
#define GBM 128
#define GBN 128
#define GBK 16
#define APITCH 20    // 80B rows, 16B-aligned, conflict-free
#define BPITCH 132   // 528B rows, 16B-aligned, conflict-free

__device__ __forceinline__ void cp_async16(void* smem_dst, const void* gsrc, int src_bytes) {
    unsigned sdst = (unsigned)__cvta_generic_to_shared(smem_dst);
    asm volatile("cp.async.ca.shared.global [%0], [%1], 16, %2;"
                 :: "r"(sdst), "l"(gsrc), "r"(src_bytes));
}
__device__ __forceinline__ void cp_async_commit() {
    asm volatile("cp.async.commit_group;");
}
template <int NN>
__device__ __forceinline__ void cp_async_wait() {
    asm volatile("cp.async.wait_group %0;" :: "n"(NN));
}

__device__ __forceinline__ void store_seg(int row, int col, float vx, float vy) {
    if (col < 256) {
        *(float2*)(g_qs + (size_t)row * 512 + col) = make_float2(vx, vy);
    } else if (col < 768) {
        *(__half2*)(g_kv + (size_t)row * 512 + (col - 256)) = __floats2half2_rn(vx, vy);
    } else {
        *(float2*)(g_qs + (size_t)row * 512 + 256 + (col - 768)) = make_float2(vx, vy);
    }
}

__global__ __launch_bounds__(256) void gemm_tc_kernel(const float* __restrict__ A, int M, int K) {
    __shared__ float As[2][GBM * APITCH];
    __shared__ float Bs[2][GBK * BPITCH];

    int tid  = threadIdx.x;
    int lane = tid & 31;
    int wid  = tid >> 5;
    int gid  = lane >> 2;
    int tig  = lane & 3;
    int warpM = wid & 1;
    int warpN = wid >> 1;

    int mBase = blockIdx.y * GBM;
    int nBase = blockIdx.x * GBN;

    // per-thread load coords (fixed across tiles)
    int aRow = tid >> 1;                 // 0..127
    int aC4  = (tid & 1) * 2;            // 0 or 2  -> two float4 each
    int gmA  = mBase + aRow;
    int okA  = (gmA < M) ? 16 : 0;
    const float* aBase = A + (size_t)((gmA < M) ? gmA : 0) * K;

    int bRow = tid >> 4;                 // 0..15
    int bC4  = (tid & 15) * 2;           // 0..30  -> two float4 each

    float c[4][4][4];
    #pragma unroll
    for (int i = 0; i < 4; i++)
        #pragma unroll
        for (int j = 0; j < 4; j++)
            #pragma unroll
            for (int r = 0; r < 4; r++) c[i][j][r] = 0.f;

    int nTiles = K / GBK;

    // prologue: load tile 0 into buffer 0
    {
        const float* as = aBase + aC4 * 4;
        cp_async16(&As[0][aRow * APITCH + aC4 * 4], as, okA);
        cp_async16(&As[0][aRow * APITCH + (aC4 + 1) * 4], as + 4, okA);
        const float* bs = g_Wc + (size_t)bRow * 1024 + nBase + bC4 * 4;
        cp_async16(&Bs[0][bRow * BPITCH + bC4 * 4], bs, 16);
        cp_async16(&Bs[0][bRow * BPITCH + (bC4 + 1) * 4], bs + 4, 16);
        cp_async_commit();
    }

    for (int kt = 0; kt < nTiles; kt++) {
        int buf = kt & 1;
        // issue loads for next tile
        if (kt + 1 < nTiles) {
            int k0 = (kt + 1) * GBK;
            int nb = buf ^ 1;
            const float* as = aBase + k0 + aC4 * 4;
            cp_async16(&As[nb][aRow * APITCH + aC4 * 4], as, okA);
            cp_async16(&As[nb][aRow * APITCH + (aC4 + 1) * 4], as + 4, okA);
            const float* bs = g_Wc + (size_t)(k0 + bRow) * 1024 + nBase + bC4 * 4;
            cp_async16(&Bs[nb][bRow * BPITCH + bC4 * 4], bs, 16);
            cp_async16(&Bs[nb][bRow * BPITCH + (bC4 + 1) * 4], bs + 4, 16);
            cp_async_commit();
            cp_async_wait<1>();
        } else {
            cp_async_wait<0>();
        }
        __syncthreads();

        const float*    Asf = As[buf];
        const unsigned* Bsb = (const unsigned*)Bs[buf];
        #pragma unroll
        for (int ks = 0; ks < 2; ks++) {
            int kk = ks * 8;
            // A fragments: load fp32 from SMEM, RNA-round to tf32 in-register
            unsigned af[4][4];
            #pragma unroll
            for (int mt = 0; mt < 4; mt++) {
                int r0 = warpM * 64 + mt * 16 + gid;
                af[mt][0] = f2tf32(Asf[(r0    ) * APITCH + kk + tig]);
                af[mt][1] = f2tf32(Asf[(r0 + 8) * APITCH + kk + tig]);
                af[mt][2] = f2tf32(Asf[(r0    ) * APITCH + kk + tig + 4]);
                af[mt][3] = f2tf32(Asf[(r0 + 8) * APITCH + kk + tig + 4]);
            }
            // B fragments: already tf32-rounded in pack_kernel
            unsigned bf[4][2];
            #pragma unroll
            for (int nt = 0; nt < 4; nt++) {
                int col = warpN * 32 + nt * 8 + gid;
                bf[nt][0] = Bsb[(kk + tig    ) * BPITCH + col];
                bf[nt][1] = Bsb[(kk + tig + 4) * BPITCH + col];
            }
            #pragma unroll
            for (int mt = 0; mt < 4; mt++)
                #pragma unroll
                for (int nt = 0; nt < 4; nt++) {
                    asm volatile(
                        "mma.sync.aligned.m16n8k8.row.col.f32.tf32.tf32.f32 "
                        "{%0,%1,%2,%3}, {%4,%5,%6,%7}, {%8,%9}, {%0,%1,%2,%3};"
                        : "+f"(c[mt][nt][0]), "+f"(c[mt][nt][1]),
                          "+f"(c[mt][nt][2]), "+f"(c[mt][nt][3])
                        : "r"(af[mt][0]), "r"(af[mt][1]), "r"(af[mt][2]), "r"(af[mt][3]),
                          "r"(bf[nt][0]), "r"(bf[nt][1]));
                }
        }
        __syncthreads();
    }

    // epilogue: bias + routed store
    #pragma unroll
    for (int nt = 0; nt < 4; nt++) {
        int col = nBase + warpN * 32 + nt * 8 + tig * 2;
        float2 bias = *(const float2*)(g_bc + col);
        #pragma unroll
        for (int mt = 0; mt < 4; mt++) {
            int row0 = mBase + warpM * 64 + mt * 16 + gid;
            if (row0 < M)
                store_seg(row0, col, c[mt][nt][0] + bias.x, c[mt][nt][1] + bias.y);
            int row1 = row0 + 8;
            if (row1 < M)
                store_seg(row1, col, c[mt][nt][2] + bias.x, c[mt][nt][3] + bias.y);
        }
    }
}

// ---------------- attention: one warp per dst node, prefetched fp16 K/V gather ----------------
__global__ __launch_bounds__(256) void attn_kernel() {
    int warp = (blockIdx.x * blockDim.x + threadIdx.x) >> 5;
    int lane = threadIdx.x & 31;
    if (warp >= N_NODES) return;

    const float* base_q = g_qs + (size_t)warp * 512 + lane * 8;
    float4 q0 = *(const float4*)(base_q);
    float4 q1 = *(const float4*)(base_q + 4);

    float m = -INFINITY, s = 0.f;
    float4 a0 = make_float4(0.f, 0.f, 0.f, 0.f);
    float4 a1 = make_float4(0.f, 0.f, 0.f, 0.f);

    int e0 = g_off[warp], e1 = g_off[warp + 1];

    uint4 kN = make_uint4(0, 0, 0, 0), vN = make_uint4(0, 0, 0, 0);
    if (e0 < e1) {
        const __half* kvb = g_kv + (size_t)g_psrc[e0] * 512 + lane * 8;
        kN = *(const uint4*)(kvb);
        vN = *(const uint4*)(kvb + 256);
    }

    for (int i = e0; i < e1; i++) {
        uint4 kc = kN, vc = vN;
        if (i + 1 < e1) {
            const __half* kvb = g_kv + (size_t)g_psrc[i + 1] * 512 + lane * 8;
            kN = *(const uint4*)(kvb);
            vN = *(const uint4*)(kvb + 256);
        }

        float2 k01 = __half22float2(*(const __half2*)&kc.x);
        float2 k23 = __half22float2(*(const __half2*)&kc.y);
        float2 k45 = __half22float2(*(const __half2*)&kc.z);
        float2 k67 = __half22float2(*(const __half2*)&kc.w);

        float d = q0.x * k01.x + q0.y * k01.y + q0.z * k23.x + q0.w * k23.y
                + q1.x * k45.x + q1.y * k45.y + q1.z * k67.x + q1.w * k67.y;
        d += __shfl_xor_sync(0xFFFFFFFFu, d, 1);
        d += __shfl_xor_sync(0xFFFFFFFFu, d, 2);
        float logit = d * 0.17677669529663687f;   // 1/sqrt(32)

        float mN = fmaxf(m, logit);
        float sc = __expf(m - mN);
        float p  = __expf(logit - mN);
        m = mN;
        s = s * sc + p;

        float2 v01 = __half22float2(*(const __half2*)&vc.x);
        float2 v23 = __half22float2(*(const __half2*)&vc.y);
        float2 v45 = __half22float2(*(const __half2*)&vc.z);
        float2 v67 = __half22float2(*(const __half2*)&vc.w);

        a0.x = a0.x * sc + p * v01.x; a0.y = a0.y * sc + p * v01.y;
        a0.z = a0.z * sc + p * v23.x; a0.w = a0.w * sc + p * v23.y;
        a1.x = a1.x * sc + p * v45.x; a1.y = a1.y * sc + p * v45.y;
        a1.z = a1.z * sc + p * v67.x; a1.w = a1.w * sc + p * v67.y;
    }

    float inv = 1.f / (s + 1e-16f);
    const float* sb = g_qs + (size_t)warp * 512 + 256 + lane * 8;
    float4 s0 = *(const float4*)(sb);
    float4 s1 = *(const float4*)(sb + 4);
    float4 o0, o1;
    o0.x = fmaxf(a0.x * inv + s0.x, 0.f);
    o0.y = fmaxf(a0.y * inv + s0.y, 0.f);
    o0.z = fmaxf(a0.z * inv + s0.z, 0.f);
    o0.w = fmaxf(a0.w * inv + s0.w, 0.f);
    o1.x = fmaxf(a1.x * inv + s1.x, 0.f);
    o1.y = fmaxf(a1.y * inv + s1.y, 0.f);
    o1.z = fmaxf(a1.z * inv + s1.z, 0.f);
    o1.w = fmaxf(a1.w * inv + s1.w, 0.f);
    float* hb = g_h + (size_t)warp * 256 + lane * 8;
    *(float4*)(hb) = o0;
    *(float4*)(hb + 4) = o1;
}

// ---------------- pooling ----------------
__global__ void zero_pool_kernel() {
    int i = blockIdx.x * blockDim.x + threadIdx.x;
    if (i < G_GRAPHS * HC) g_pool[i] = 0.f;
    if (i < G_GRAPHS) g_gcnt[i] = 0;
}

__global__ __launch_bounds__(256) void pool_kernel(const int* __restrict__ batch) {
    int c = threadIdx.x;
    int per = (N_NODES + gridDim.x - 1) / gridDim.x;
    int start = blockIdx.x * per;
    int end = min(N_NODES, start + per);
    if (start >= end) return;
    int cur = batch[start];
    float acc = 0.f;
    int cnt = 0;
    for (int i = start; i < end; i++) {
        int b = batch[i];
        if (b != cur) {
            atomicAdd(&g_pool[cur * HC + c], acc);
            if (c == 0) atomicAdd(&g_gcnt[cur], cnt);
            acc = 0.f; cnt = 0; cur = b;
        }
        acc += g_h[(size_t)i * HC + c];
        cnt++;
    }
    atomicAdd(&g_pool[cur * HC + c], acc);
    if (c == 0) atomicAdd(&g_gcnt[cur], cnt);
}

__global__ void fc_kernel(const float* __restrict__ Wfc, const float* __restrict__ bfc,
                          float* __restrict__ out) {
    int g = blockIdx.x;
    int o = threadIdx.x;
    __shared__ float p[HC];
    float inv = 1.f / fmaxf((float)g_gcnt[g], 1.f);
    for (int i = o; i < HC; i += OUT_F) p[i] = g_pool[g * HC + i] * inv;
    __syncthreads();
    float acc = bfc[o];
    #pragma unroll 8
    for (int f = 0; f < HC; f++) acc += p[f] * Wfc[f * OUT_F + o];
    out[g * OUT_F + o] = acc;
}

// ---------------- launch ----------------
extern "C" void kernel_launch(void* const* d_in, const int* in_sizes, int n_in,
                              void* d_out, int out_size) {
    const float* x    = (const float*)d_in[0];
    const int*   ei   = (const int*)d_in[1];
    const int*   src  = ei;
    const int*   dst  = ei + N_EDGES;
    const int*   batch = (const int*)d_in[2];
    const float* Wq0 = (const float*)d_in[3];
    const float* bq0 = (const float*)d_in[4];
    const float* Wk0 = (const float*)d_in[5];
    const float* bk0 = (const float*)d_in[6];
    const float* Wv0 = (const float*)d_in[7];
    const float* bv0 = (const float*)d_in[8];
    const float* Ws0 = (const float*)d_in[9];
    const float* bs0 = (const float*)d_in[10];
    const float* Wq  = (const float*)d_in[11];
    const float* bq  = (const float*)d_in[12];
    const float* Wk  = (const float*)d_in[13];
    const float* bk  = (const float*)d_in[14];
    const float* Wv  = (const float*)d_in[15];
    const float* bv  = (const float*)d_in[16];
    const float* Ws  = (const float*)d_in[17];
    const float* bs  = (const float*)d_in[18];
    const float* Wfc = (const float*)d_in[19];
    const float* bfc = (const float*)d_in[20];
    float* out = (float*)d_out;

    const int TB = 256;
    // CSR build (dst-sorted adjacency)
    zero_csr_kernel<<<(N_NODES + TB - 1) / TB, TB>>>();
    hist_kernel<<<(N_EDGES + TB - 1) / TB, TB>>>(dst);
    scan_kernel<<<1, 1024>>>();
    scatter_kernel<<<(N_EDGES + TB - 1) / TB, TB>>>(src, dst);

    dim3 ggrid(1024 / GBN, (N_NODES + GBM - 1) / GBM);
    int attnBlocks = (N_NODES + 7) / 8;

    // layer 0 (IN_F -> HC)
    pack_kernel<<<(IN_F * 1024 + TB - 1) / TB, TB>>>(Wq0, Wk0, Wv0, Ws0, bq0, bk0, bv0, bs0, IN_F);
    gemm_tc_kernel<<<ggrid, 256>>>(x, N_NODES, IN_F);
    attn_kernel<<<attnBlocks, 256>>>();

    // layers 1..3 (HC -> HC)
    float* hptr = nullptr;
    cudaGetSymbolAddress((void**)&hptr, g_h);
    for (int l = 0; l < NLAYERS - 1; l++) {
        const float* wq = Wq + (size_t)l * HC * HC;
        const float* wk = Wk + (size_t)l * HC * HC;
        const float* wv = Wv + (size_t)l * HC * HC;
        const float* ws = Ws + (size_t)l * HC * HC;
        pack_kernel<<<(HC * 1024 + TB - 1) / TB, TB>>>(wq, wk, wv, ws,
                                                       bq + l * HC, bk + l * HC,
                                                       bv + l * HC, bs + l * HC, HC);
        gemm_tc_kernel<<<ggrid, 256>>>(hptr, N_NODES, HC);
        attn_kernel<<<attnBlocks, 256>>>();
    }

    // pooling + fc
    zero_pool_kernel<<<(G_GRAPHS * HC + TB - 1) / TB, TB>>>();
    pool_kernel<<<256, 256>>>(batch);
    fc_kernel<<<G_GRAPHS, OUT_F>>>(Wfc, bfc, out);
}

// round 9
// speedup vs baseline: 2.9089x; 1.3193x over previous
#include <cuda_runtime.h>
#include <cuda_fp16.h>
#include <math.h>

#define N_NODES 50000
#define N_EDGES 800000
#define IN_F    128
#define HC      256
#define G_GRAPHS 64
#define OUT_F   64
#define NLAYERS 4

// ---------------- scratch (static device allocations; no cudaMalloc) ----------------
__device__ float  g_qs[(size_t)N_NODES * 512];    // [q|s] per node, fp32
__device__ __half g_kv[(size_t)N_NODES * 512];    // [k|v] per node, fp16
__device__ __half g_hh[(size_t)N_NODES * HC];     // layer activations, fp16
__device__ __half g_xh[(size_t)N_NODES * IN_F];   // input x converted to fp16
__device__ __half g_Wc[1024 * 256];               // packed W^T [1024 cols][K], fp16
__device__ float  g_bc[1024];
__device__ int    g_cnt[N_NODES];
__device__ int    g_cur[N_NODES];
__device__ int    g_off[N_NODES + 1];
__device__ int    g_psrc[N_EDGES];
__device__ float  g_pool[G_GRAPHS * HC];
__device__ int    g_gcnt[G_GRAPHS];

// ---------------- CSR build ----------------
__global__ void zero_csr_kernel() {
    int i = blockIdx.x * blockDim.x + threadIdx.x;
    if (i < N_NODES) { g_cnt[i] = 0; g_cur[i] = 0; }
}

__global__ void hist_kernel(const int* __restrict__ dst) {
    int e = blockIdx.x * blockDim.x + threadIdx.x;
    if (e < N_EDGES) atomicAdd(&g_cnt[dst[e]], 1);
}

__global__ void scan_kernel() {
    __shared__ int buf[1024];
    __shared__ int carry;
    int tid = threadIdx.x;
    if (tid == 0) carry = 0;
    __syncthreads();
    for (int base = 0; base < N_NODES; base += 1024) {
        int i = base + tid;
        int v = (i < N_NODES) ? g_cnt[i] : 0;
        buf[tid] = v;
        __syncthreads();
        #pragma unroll
        for (int ofs = 1; ofs < 1024; ofs <<= 1) {
            int t = (tid >= ofs) ? buf[tid - ofs] : 0;
            __syncthreads();
            buf[tid] += t;
            __syncthreads();
        }
        int excl = buf[tid] - v + carry;
        if (i < N_NODES) g_off[i] = excl;
        __syncthreads();
        if (tid == 1023) carry += buf[1023];
        __syncthreads();
    }
    if (tid == 0) g_off[N_NODES] = carry;
}

__global__ void scatter_kernel(const int* __restrict__ src, const int* __restrict__ dst) {
    int e = blockIdx.x * blockDim.x + threadIdx.x;
    if (e < N_EDGES) {
        int d = dst[e];
        int p = atomicAdd(&g_cur[d], 1);
        g_psrc[g_off[d] + p] = src[e];
    }
}

// ---------------- x -> fp16 conversion (once) ----------------
__global__ void xcvt_kernel(const float* __restrict__ x) {
    int i = blockIdx.x * blockDim.x + threadIdx.x;   // over N*IN_F/2 half2
    int total = N_NODES * IN_F / 2;
    if (i < total) {
        float2 v = *(const float2*)(x + (size_t)i * 2);
        *(__half2*)(g_xh + (size_t)i * 2) = __floats2half2_rn(v.x, v.y);
    }
}

// ---------------- weight packing: [F,256]x4 -> W^T [1024][F], fp16 ----------------
__global__ void pack_kernel(const float* __restrict__ Wq, const float* __restrict__ Wk,
                            const float* __restrict__ Wv, const float* __restrict__ Ws,
                            const float* __restrict__ bq, const float* __restrict__ bk,
                            const float* __restrict__ bv, const float* __restrict__ bs,
                            int F) {
    int idx = blockIdx.x * blockDim.x + threadIdx.x;
    int total = F * 1024;
    if (idx < total) {
        int f   = idx & (F - 1);       // F is 128 or 256 (power of 2)
        int col = idx / F;             // 0..1023
        int sel = col >> 8;
        int c   = col & 255;
        const float* W = (sel == 0) ? Wq : (sel == 1) ? Wk : (sel == 2) ? Wv : Ws;
        g_Wc[idx] = __float2half_rn(W[f * 256 + c]);   // g_Wc[col*F + f]
    }
    if (idx < 1024) {
        int sel = idx >> 8, c = idx & 255;
        const float* b = (sel == 0) ? bq : (sel == 1) ? bk : (sel == 2) ? bv : bs;
        g_bc[idx] = b[c];
    }
}

// ---------------- fp16 tensor-core GEMM (m16n8k16), cp.async double-buffered ----------------
// C[M,1024] = A[M,K] @ W[K,1024] + bc  (A fp16 row-major, W^T fp16 in g_Wc), fp32 accum.
#define GBM 128
#define GBN 128
#define GBK 32
#define HPITCH 40     // 40 halfs = 80B row pitch; bank (20*row+tig)%32 bijective -> conflict-free

__device__ __forceinline__ void cp_async16(void* smem_dst, const void* gsrc, int src_bytes) {
    unsigned sdst = (unsigned)__cvta_generic_to_shared(smem_dst);
    asm volatile("cp.async.ca.shared.global [%0], [%1], 16, %2;"
                 :: "r"(sdst), "l"(gsrc), "r"(src_bytes));
}
__device__ __forceinline__ void cp_async_commit() {
    asm volatile("cp.async.commit_group;");
}
template <int NN>
__device__ __forceinline__ void cp_async_wait() {
    asm volatile("cp.async.wait_group %0;" :: "n"(NN));
}

__device__ __forceinline__ void store_seg(int row, int col, float vx, float vy) {
    if (col < 256) {
        *(float2*)(g_qs + (size_t)row * 512 + col) = make_float2(vx, vy);
    } else if (col < 768) {
        *(__half2*)(g_kv + (size_t)row * 512 + (col - 256)) = __floats2half2_rn(vx, vy);
    } else {
        *(float2*)(g_qs + (size_t)row * 512 + 256 + (col - 768)) = make_float2(vx, vy);
    }
}

__global__ __launch_bounds__(256) void gemm_tc_kernel(const __half* __restrict__ A, int M, int K) {
    __shared__ __half As[2][GBM * HPITCH];   // 128 rows x 32 k (+pad)
    __shared__ __half Bs[2][GBN * HPITCH];   // 128 cols x 32 k (+pad)

    int tid  = threadIdx.x;
    int lane = tid & 31;
    int wid  = tid >> 5;
    int gid  = lane >> 2;   // 0..7
    int tig  = lane & 3;    // 0..3
    int warpM = wid & 1;    // 64 rows each
    int warpN = wid >> 1;   // 32 cols each

    int mBase = blockIdx.y * GBM;
    int nBase = blockIdx.x * GBN;

    // A loads: row = tid>>1 (0..127), chunks 2*(tid&1), +1 ; each chunk = 8 halfs (16B)
    int aRow = tid >> 1;
    int aCk  = (tid & 1) * 2;
    int gmA  = mBase + aRow;
    int okA  = (gmA < M) ? 16 : 0;
    const __half* aBase = A + (size_t)((gmA < M) ? gmA : 0) * K;

    // B loads: col = tid>>1, chunks 2*(tid&1), +1
    int bCol = tid >> 1;
    int bCk  = (tid & 1) * 2;
    const __half* bBase = g_Wc + (size_t)(nBase + bCol) * K;

    float c[4][4][4];
    #pragma unroll
    for (int i = 0; i < 4; i++)
        #pragma unroll
        for (int j = 0; j < 4; j++)
            #pragma unroll
            for (int r = 0; r < 4; r++) c[i][j][r] = 0.f;

    int nTiles = K / GBK;

    // prologue: tile 0 -> buffer 0
    {
        cp_async16(&As[0][aRow * HPITCH + aCk * 8], aBase + aCk * 8, okA);
        cp_async16(&As[0][aRow * HPITCH + (aCk + 1) * 8], aBase + (aCk + 1) * 8, okA);
        cp_async16(&Bs[0][bCol * HPITCH + bCk * 8], bBase + bCk * 8, 16);
        cp_async16(&Bs[0][bCol * HPITCH + (bCk + 1) * 8], bBase + (bCk + 1) * 8, 16);
        cp_async_commit();
    }

    for (int kt = 0; kt < nTiles; kt++) {
        int buf = kt & 1;
        if (kt + 1 < nTiles) {
            int k0 = (kt + 1) * GBK;
            int nb = buf ^ 1;
            cp_async16(&As[nb][aRow * HPITCH + aCk * 8], aBase + k0 + aCk * 8, okA);
            cp_async16(&As[nb][aRow * HPITCH + (aCk + 1) * 8], aBase + k0 + (aCk + 1) * 8, okA);
            cp_async16(&Bs[nb][bCol * HPITCH + bCk * 8], bBase + k0 + bCk * 8, 16);
            cp_async16(&Bs[nb][bCol * HPITCH + (bCk + 1) * 8], bBase + k0 + (bCk + 1) * 8, 16);
            cp_async_commit();
            cp_async_wait<1>();
        } else {
            cp_async_wait<0>();
        }
        __syncthreads();

        const __half* Asb = As[buf];
        const __half* Bsb = Bs[buf];
        #pragma unroll
        for (int ks = 0; ks < 2; ks++) {
            int kk = ks * 16;
            // A fragments (m16n8k16): a0=(r,kk+2t) a1=(r+8,kk+2t) a2=(r,kk+2t+8) a3=(r+8,kk+2t+8)
            unsigned af[4][4];
            #pragma unroll
            for (int mt = 0; mt < 4; mt++) {
                int r0 = warpM * 64 + mt * 16 + gid;
                af[mt][0] = *(const unsigned*)&Asb[(r0    ) * HPITCH + kk + tig * 2];
                af[mt][1] = *(const unsigned*)&Asb[(r0 + 8) * HPITCH + kk + tig * 2];
                af[mt][2] = *(const unsigned*)&Asb[(r0    ) * HPITCH + kk + tig * 2 + 8];
                af[mt][3] = *(const unsigned*)&Asb[(r0 + 8) * HPITCH + kk + tig * 2 + 8];
            }
            // B fragments: b0=(k=kk+2t, n) b1=(k=kk+2t+8, n), n = col
            unsigned bf[4][2];
            #pragma unroll
            for (int nt = 0; nt < 4; nt++) {
                int col = warpN * 32 + nt * 8 + gid;
                bf[nt][0] = *(const unsigned*)&Bsb[col * HPITCH + kk + tig * 2];
                bf[nt][1] = *(const unsigned*)&Bsb[col * HPITCH + kk + tig * 2 + 8];
            }
            #pragma unroll
            for (int mt = 0; mt < 4; mt++)
                #pragma unroll
                for (int nt = 0; nt < 4; nt++) {
                    asm volatile(
                        "mma.sync.aligned.m16n8k16.row.col.f32.f16.f16.f32 "
                        "{%0,%1,%2,%3}, {%4,%5,%6,%7}, {%8,%9}, {%0,%1,%2,%3};"
                        : "+f"(c[mt][nt][0]), "+f"(c[mt][nt][1]),
                          "+f"(c[mt][nt][2]), "+f"(c[mt][nt][3])
                        : "r"(af[mt][0]), "r"(af[mt][1]), "r"(af[mt][2]), "r"(af[mt][3]),
                          "r"(bf[nt][0]), "r"(bf[nt][1]));
                }
        }
        __syncthreads();
    }

    // epilogue: bias + routed store
    #pragma unroll
    for (int nt = 0; nt < 4; nt++) {
        int col = nBase + warpN * 32 + nt * 8 + tig * 2;
        float2 bias = *(const float2*)(g_bc + col);
        #pragma unroll
        for (int mt = 0; mt < 4; mt++) {
            int row0 = mBase + warpM * 64 + mt * 16 + gid;
            if (row0 < M)
                store_seg(row0, col, c[mt][nt][0] + bias.x, c[mt][nt][1] + bias.y);
            int row1 = row0 + 8;
            if (row1 < M)
                store_seg(row1, col, c[mt][nt][2] + bias.x, c[mt][nt][3] + bias.y);
        }
    }
}

// ---------------- attention: one warp per dst node, prefetched fp16 K/V gather ----------------
__global__ __launch_bounds__(256) void attn_kernel() {
    int warp = (blockIdx.x * blockDim.x + threadIdx.x) >> 5;
    int lane = threadIdx.x & 31;
    if (warp >= N_NODES) return;

    const float* base_q = g_qs + (size_t)warp * 512 + lane * 8;
    float4 q0 = *(const float4*)(base_q);
    float4 q1 = *(const float4*)(base_q + 4);

    float m = -INFINITY, s = 0.f;
    float4 a0 = make_float4(0.f, 0.f, 0.f, 0.f);
    float4 a1 = make_float4(0.f, 0.f, 0.f, 0.f);

    int e0 = g_off[warp], e1 = g_off[warp + 1];

    uint4 kN = make_uint4(0, 0, 0, 0), vN = make_uint4(0, 0, 0, 0);
    if (e0 < e1) {
        const __half* kvb = g_kv + (size_t)g_psrc[e0] * 512 + lane * 8;
        kN = *(const uint4*)(kvb);
        vN = *(const uint4*)(kvb + 256);
    }

    for (int i = e0; i < e1; i++) {
        uint4 kc = kN, vc = vN;
        if (i + 1 < e1) {
            const __half* kvb = g_kv + (size_t)g_psrc[i + 1] * 512 + lane * 8;
            kN = *(const uint4*)(kvb);
            vN = *(const uint4*)(kvb + 256);
        }

        float2 k01 = __half22float2(*(const __half2*)&kc.x);
        float2 k23 = __half22float2(*(const __half2*)&kc.y);
        float2 k45 = __half22float2(*(const __half2*)&kc.z);
        float2 k67 = __half22float2(*(const __half2*)&kc.w);

        float d = q0.x * k01.x + q0.y * k01.y + q0.z * k23.x + q0.w * k23.y
                + q1.x * k45.x + q1.y * k45.y + q1.z * k67.x + q1.w * k67.y;
        d += __shfl_xor_sync(0xFFFFFFFFu, d, 1);
        d += __shfl_xor_sync(0xFFFFFFFFu, d, 2);
        float logit = d * 0.17677669529663687f;   // 1/sqrt(32)

        float mN = fmaxf(m, logit);
        float sc = __expf(m - mN);
        float p  = __expf(logit - mN);
        m = mN;
        s = s * sc + p;

        float2 v01 = __half22float2(*(const __half2*)&vc.x);
        float2 v23 = __half22float2(*(const __half2*)&vc.y);
        float2 v45 = __half22float2(*(const __half2*)&vc.z);
        float2 v67 = __half22float2(*(const __half2*)&vc.w);

        a0.x = a0.x * sc + p * v01.x; a0.y = a0.y * sc + p * v01.y;
        a0.z = a0.z * sc + p * v23.x; a0.w = a0.w * sc + p * v23.y;
        a1.x = a1.x * sc + p * v45.x; a1.y = a1.y * sc + p * v45.y;
        a1.z = a1.z * sc + p * v67.x; a1.w = a1.w * sc + p * v67.y;
    }

    float inv = 1.f / (s + 1e-16f);
    const float* sb = g_qs + (size_t)warp * 512 + 256 + lane * 8;
    float4 s0 = *(const float4*)(sb);
    float4 s1 = *(const float4*)(sb + 4);
    float r0 = fmaxf(a0.x * inv + s0.x, 0.f);
    float r1 = fmaxf(a0.y * inv + s0.y, 0.f);
    float r2 = fmaxf(a0.z * inv + s0.z, 0.f);
    float r3 = fmaxf(a0.w * inv + s0.w, 0.f);
    float r4 = fmaxf(a1.x * inv + s1.x, 0.f);
    float r5 = fmaxf(a1.y * inv + s1.y, 0.f);
    float r6 = fmaxf(a1.z * inv + s1.z, 0.f);
    float r7 = fmaxf(a1.w * inv + s1.w, 0.f);

    __half* hb = g_hh + (size_t)warp * 256 + lane * 8;
    uint4 packed;
    *(__half2*)&packed.x = __floats2half2_rn(r0, r1);
    *(__half2*)&packed.y = __floats2half2_rn(r2, r3);
    *(__half2*)&packed.z = __floats2half2_rn(r4, r5);
    *(__half2*)&packed.w = __floats2half2_rn(r6, r7);
    *(uint4*)hb = packed;
}

// ---------------- pooling ----------------
__global__ void zero_pool_kernel() {
    int i = blockIdx.x * blockDim.x + threadIdx.x;
    if (i < G_GRAPHS * HC) g_pool[i] = 0.f;
    if (i < G_GRAPHS) g_gcnt[i] = 0;
}

__global__ __launch_bounds__(256) void pool_kernel(const int* __restrict__ batch) {
    int c = threadIdx.x;
    int per = (N_NODES + gridDim.x - 1) / gridDim.x;
    int start = blockIdx.x * per;
    int end = min(N_NODES, start + per);
    if (start >= end) return;
    int cur = batch[start];
    float acc = 0.f;
    int cnt = 0;
    for (int i = start; i < end; i++) {
        int b = batch[i];
        if (b != cur) {
            atomicAdd(&g_pool[cur * HC + c], acc);
            if (c == 0) atomicAdd(&g_gcnt[cur], cnt);
            acc = 0.f; cnt = 0; cur = b;
        }
        acc += __half2float(g_hh[(size_t)i * HC + c]);
        cnt++;
    }
    atomicAdd(&g_pool[cur * HC + c], acc);
    if (c == 0) atomicAdd(&g_gcnt[cur], cnt);
}

__global__ void fc_kernel(const float* __restrict__ Wfc, const float* __restrict__ bfc,
                          float* __restrict__ out) {
    int g = blockIdx.x;
    int o = threadIdx.x;
    __shared__ float p[HC];
    float inv = 1.f / fmaxf((float)g_gcnt[g], 1.f);
    for (int i = o; i < HC; i += OUT_F) p[i] = g_pool[g * HC + i] * inv;
    __syncthreads();
    float acc = bfc[o];
    #pragma unroll 8
    for (int f = 0; f < HC; f++) acc += p[f] * Wfc[f * OUT_F + o];
    out[g * OUT_F + o] = acc;
}

// ---------------- launch ----------------
extern "C" void kernel_launch(void* const* d_in, const int* in_sizes, int n_in,
                              void* d_out, int out_size) {
    const float* x    = (const float*)d_in[0];
    const int*   ei   = (const int*)d_in[1];
    const int*   src  = ei;
    const int*   dst  = ei + N_EDGES;
    const int*   batch = (const int*)d_in[2];
    const float* Wq0 = (const float*)d_in[3];
    const float* bq0 = (const float*)d_in[4];
    const float* Wk0 = (const float*)d_in[5];
    const float* bk0 = (const float*)d_in[6];
    const float* Wv0 = (const float*)d_in[7];
    const float* bv0 = (const float*)d_in[8];
    const float* Ws0 = (const float*)d_in[9];
    const float* bs0 = (const float*)d_in[10];
    const float* Wq  = (const float*)d_in[11];
    const float* bq  = (const float*)d_in[12];
    const float* Wk  = (const float*)d_in[13];
    const float* bk  = (const float*)d_in[14];
    const float* Wv  = (const float*)d_in[15];
    const float* bv  = (const float*)d_in[16];
    const float* Ws  = (const float*)d_in[17];
    const float* bs  = (const float*)d_in[18];
    const float* Wfc = (const float*)d_in[19];
    const float* bfc = (const float*)d_in[20];
    float* out = (float*)d_out;

    const int TB = 256;
    // CSR build (dst-sorted adjacency)
    zero_csr_kernel<<<(N_NODES + TB - 1) / TB, TB>>>();
    hist_kernel<<<(N_EDGES + TB - 1) / TB, TB>>>(dst);
    scan_kernel<<<1, 1024>>>();
    scatter_kernel<<<(N_EDGES + TB - 1) / TB, TB>>>(src, dst);

    // x -> fp16 once
    xcvt_kernel<<<(N_NODES * IN_F / 2 + TB - 1) / TB, TB>>>(x);

    dim3 ggrid(1024 / GBN, (N_NODES + GBM - 1) / GBM);
    int attnBlocks = (N_NODES + 7) / 8;

    __half* xh = nullptr;
    __half* hh = nullptr;
    cudaGetSymbolAddress((void**)&xh, g_xh);
    cudaGetSymbolAddress((void**)&hh, g_hh);

    // layer 0 (IN_F -> HC)
    pack_kernel<<<(IN_F * 1024 + TB - 1) / TB, TB>>>(Wq0, Wk0, Wv0, Ws0, bq0, bk0, bv0, bs0, IN_F);
    gemm_tc_kernel<<<ggrid, 256>>>(xh, N_NODES, IN_F);
    attn_kernel<<<attnBlocks, 256>>>();

    // layers 1..3 (HC -> HC)
    for (int l = 0; l < NLAYERS - 1; l++) {
        const float* wq = Wq + (size_t)l * HC * HC;
        const float* wk = Wk + (size_t)l * HC * HC;
        const float* wv = Wv + (size_t)l * HC * HC;
        const float* ws = Ws + (size_t)l * HC * HC;
        pack_kernel<<<(HC * 1024 + TB - 1) / TB, TB>>>(wq, wk, wv, ws,
                                                       bq + l * HC, bk + l * HC,
                                                       bv + l * HC, bs + l * HC, HC);
        gemm_tc_kernel<<<ggrid, 256>>>(hh, N_NODES, HC);
        attn_kernel<<<attnBlocks, 256>>>();
    }

    // pooling + fc
    zero_pool_kernel<<<(G_GRAPHS * HC + TB - 1) / TB, TB>>>();
    pool_kernel<<<256, 256>>>(batch);
    fc_kernel<<<G_GRAPHS, OUT_F>>>(Wfc, bfc, out);
}

// round 10
// speedup vs baseline: 3.0221x; 1.0389x over previous
#include <cuda_runtime.h>
#include <cuda_fp16.h>
#include <math.h>

#define N_NODES 50000
#define N_EDGES 800000
#define IN_F    128
#define HC      256
#define G_GRAPHS 64
#define OUT_F   64
#define NLAYERS 4

// ---------------- scratch (static device allocations; no cudaMalloc) ----------------
__device__ float  g_qs[(size_t)N_NODES * 512];    // [q|s] per node, fp32
__device__ __half g_kv[(size_t)N_NODES * 512];    // [k|v] per node, fp16
__device__ __half g_hh[(size_t)N_NODES * HC];     // layer activations, fp16
__device__ __half g_xh[(size_t)N_NODES * IN_F];   // input x converted to fp16
__device__ __half g_Wc[1024 * 256];               // packed W^T [1024 cols][K], fp16
__device__ float  g_bc[1024];
__device__ int    g_cnt[N_NODES];
__device__ int    g_cur[N_NODES];
__device__ int    g_off[N_NODES + 1];
__device__ int    g_psrc[N_EDGES];
__device__ float  g_pool[G_GRAPHS * HC];
__device__ int    g_gcnt[G_GRAPHS];

// ---------------- CSR build ----------------
__global__ void zero_csr_kernel() {
    int i = blockIdx.x * blockDim.x + threadIdx.x;
    if (i < N_NODES) { g_cnt[i] = 0; g_cur[i] = 0; }
}

__global__ void hist_kernel(const int* __restrict__ dst) {
    int e = blockIdx.x * blockDim.x + threadIdx.x;
    if (e < N_EDGES) atomicAdd(&g_cnt[dst[e]], 1);
}

__global__ void scan_kernel() {
    __shared__ int buf[1024];
    __shared__ int carry;
    int tid = threadIdx.x;
    if (tid == 0) carry = 0;
    __syncthreads();
    for (int base = 0; base < N_NODES; base += 1024) {
        int i = base + tid;
        int v = (i < N_NODES) ? g_cnt[i] : 0;
        buf[tid] = v;
        __syncthreads();
        #pragma unroll
        for (int ofs = 1; ofs < 1024; ofs <<= 1) {
            int t = (tid >= ofs) ? buf[tid - ofs] : 0;
            __syncthreads();
            buf[tid] += t;
            __syncthreads();
        }
        int excl = buf[tid] - v + carry;
        if (i < N_NODES) g_off[i] = excl;
        __syncthreads();
        if (tid == 1023) carry += buf[1023];
        __syncthreads();
    }
    if (tid == 0) g_off[N_NODES] = carry;
}

__global__ void scatter_kernel(const int* __restrict__ src, const int* __restrict__ dst) {
    int e = blockIdx.x * blockDim.x + threadIdx.x;
    if (e < N_EDGES) {
        int d = dst[e];
        int p = atomicAdd(&g_cur[d], 1);
        g_psrc[g_off[d] + p] = src[e];
    }
}

// ---------------- x -> fp16 conversion (once) ----------------
__global__ void xcvt_kernel(const float* __restrict__ x) {
    int i = blockIdx.x * blockDim.x + threadIdx.x;
    int total = N_NODES * IN_F / 2;
    if (i < total) {
        float2 v = *(const float2*)(x + (size_t)i * 2);
        *(__half2*)(g_xh + (size_t)i * 2) = __floats2half2_rn(v.x, v.y);
    }
}

// ---------------- weight packing: [F,256]x4 -> W^T [1024][F], fp16 ----------------
__global__ void pack_kernel(const float* __restrict__ Wq, const float* __restrict__ Wk,
                            const float* __restrict__ Wv, const float* __restrict__ Ws,
                            const float* __restrict__ bq, const float* __restrict__ bk,
                            const float* __restrict__ bv, const float* __restrict__ bs,
                            int F) {
    int idx = blockIdx.x * blockDim.x + threadIdx.x;
    int total = F * 1024;
    if (idx < total) {
        int f   = idx & (F - 1);
        int col = idx / F;
        int sel = col >> 8;
        int c   = col & 255;
        const float* W = (sel == 0) ? Wq : (sel == 1) ? Wk : (sel == 2) ? Wv : Ws;
        g_Wc[idx] = __float2half_rn(W[f * 256 + c]);
    }
    if (idx < 1024) {
        int sel = idx >> 8, c = idx & 255;
        const float* b = (sel == 0) ? bq : (sel == 1) ? bk : (sel == 2) ? bv : bs;
        g_bc[idx] = b[c];
    }
}

// ---------------- fp16 tensor-core GEMM (m16n8k16), cp.async + ldmatrix ----------------
#define GBM 128
#define GBN 128
#define GBK 32
#define HPITCH 40     // 40 halfs = 80B pitch; conflict-free for ldmatrix 8-row access

__device__ __forceinline__ void cp_async16(void* smem_dst, const void* gsrc, int src_bytes) {
    unsigned sdst = (unsigned)__cvta_generic_to_shared(smem_dst);
    asm volatile("cp.async.ca.shared.global [%0], [%1], 16, %2;"
                 :: "r"(sdst), "l"(gsrc), "r"(src_bytes));
}
__device__ __forceinline__ void cp_async_commit() {
    asm volatile("cp.async.commit_group;");
}
template <int NN>
__device__ __forceinline__ void cp_async_wait() {
    asm volatile("cp.async.wait_group %0;" :: "n"(NN));
}

__device__ __forceinline__ void ldsm_x4(unsigned& r0, unsigned& r1, unsigned& r2, unsigned& r3,
                                        unsigned addr) {
    asm volatile("ldmatrix.sync.aligned.m8n8.x4.shared.b16 {%0,%1,%2,%3}, [%4];"
                 : "=r"(r0), "=r"(r1), "=r"(r2), "=r"(r3) : "r"(addr));
}
__device__ __forceinline__ void ldsm_x2(unsigned& r0, unsigned& r1, unsigned addr) {
    asm volatile("ldmatrix.sync.aligned.m8n8.x2.shared.b16 {%0,%1}, [%2];"
                 : "=r"(r0), "=r"(r1) : "r"(addr));
}

__device__ __forceinline__ void store_seg(int row, int col, float vx, float vy) {
    if (col < 256) {
        *(float2*)(g_qs + (size_t)row * 512 + col) = make_float2(vx, vy);
    } else if (col < 768) {
        *(__half2*)(g_kv + (size_t)row * 512 + (col - 256)) = __floats2half2_rn(vx, vy);
    } else {
        *(float2*)(g_qs + (size_t)row * 512 + 256 + (col - 768)) = make_float2(vx, vy);
    }
}

__global__ __launch_bounds__(256) void gemm_tc_kernel(const __half* __restrict__ A, int M, int K) {
    __shared__ __half As[2][GBM * HPITCH];
    __shared__ __half Bs[2][GBN * HPITCH];

    int tid  = threadIdx.x;
    int lane = tid & 31;
    int wid  = tid >> 5;
    int gid  = lane >> 2;
    int tig  = lane & 3;
    int warpM = wid & 1;
    int warpN = wid >> 1;

    int mBase = blockIdx.y * GBM;
    int nBase = blockIdx.x * GBN;

    // cp.async load coords
    int aRow = tid >> 1;
    int aCk  = (tid & 1) * 2;
    int gmA  = mBase + aRow;
    int okA  = (gmA < M) ? 16 : 0;
    const __half* aBase = A + (size_t)((gmA < M) ? gmA : 0) * K;
    int bCol = tid >> 1;
    int bCk  = (tid & 1) * 2;
    const __half* bBase = g_Wc + (size_t)(nBase + bCol) * K;

    // ldmatrix per-thread address offsets
    int aRowOff = lane & 15;
    int aKOff   = (lane >> 4) << 3;        // 0 or 8
    int bColOff = lane & 7;
    int bKOff   = ((lane >> 3) & 1) << 3;  // 0 or 8 (lanes>=16 repeat: valid, ignored)

    float c[4][4][4];
    #pragma unroll
    for (int i = 0; i < 4; i++)
        #pragma unroll
        for (int j = 0; j < 4; j++)
            #pragma unroll
            for (int r = 0; r < 4; r++) c[i][j][r] = 0.f;

    int nTiles = K / GBK;

    {
        cp_async16(&As[0][aRow * HPITCH + aCk * 8], aBase + aCk * 8, okA);
        cp_async16(&As[0][aRow * HPITCH + (aCk + 1) * 8], aBase + (aCk + 1) * 8, okA);
        cp_async16(&Bs[0][bCol * HPITCH + bCk * 8], bBase + bCk * 8, 16);
        cp_async16(&Bs[0][bCol * HPITCH + (bCk + 1) * 8], bBase + (bCk + 1) * 8, 16);
        cp_async_commit();
    }

    for (int kt = 0; kt < nTiles; kt++) {
        int buf = kt & 1;
        if (kt + 1 < nTiles) {
            int k0 = (kt + 1) * GBK;
            int nb = buf ^ 1;
            cp_async16(&As[nb][aRow * HPITCH + aCk * 8], aBase + k0 + aCk * 8, okA);
            cp_async16(&As[nb][aRow * HPITCH + (aCk + 1) * 8], aBase + k0 + (aCk + 1) * 8, okA);
            cp_async16(&Bs[nb][bCol * HPITCH + bCk * 8], bBase + k0 + bCk * 8, 16);
            cp_async16(&Bs[nb][bCol * HPITCH + (bCk + 1) * 8], bBase + k0 + (bCk + 1) * 8, 16);
            cp_async_commit();
            cp_async_wait<1>();
        } else {
            cp_async_wait<0>();
        }
        __syncthreads();

        unsigned asb32 = (unsigned)__cvta_generic_to_shared(&As[buf][0]);
        unsigned bsb32 = (unsigned)__cvta_generic_to_shared(&Bs[buf][0]);
        #pragma unroll
        for (int ks = 0; ks < 2; ks++) {
            int kk = ks * 16;
            unsigned af[4][4];
            #pragma unroll
            for (int mt = 0; mt < 4; mt++) {
                unsigned addr = asb32 +
                    ((warpM * 64 + mt * 16 + aRowOff) * HPITCH + kk + aKOff) * 2;
                ldsm_x4(af[mt][0], af[mt][1], af[mt][2], af[mt][3], addr);
            }
            unsigned bf[4][2];
            #pragma unroll
            for (int nt = 0; nt < 4; nt++) {
                unsigned addr = bsb32 +
                    ((warpN * 32 + nt * 8 + bColOff) * HPITCH + kk + bKOff) * 2;
                ldsm_x2(bf[nt][0], bf[nt][1], addr);
            }
            #pragma unroll
            for (int mt = 0; mt < 4; mt++)
                #pragma unroll
                for (int nt = 0; nt < 4; nt++) {
                    asm volatile(
                        "mma.sync.aligned.m16n8k16.row.col.f32.f16.f16.f32 "
                        "{%0,%1,%2,%3}, {%4,%5,%6,%7}, {%8,%9}, {%0,%1,%2,%3};"
                        : "+f"(c[mt][nt][0]), "+f"(c[mt][nt][1]),
                          "+f"(c[mt][nt][2]), "+f"(c[mt][nt][3])
                        : "r"(af[mt][0]), "r"(af[mt][1]), "r"(af[mt][2]), "r"(af[mt][3]),
                          "r"(bf[nt][0]), "r"(bf[nt][1]));
                }
        }
        __syncthreads();
    }

    #pragma unroll
    for (int nt = 0; nt < 4; nt++) {
        int col = nBase + warpN * 32 + nt * 8 + tig * 2;
        float2 bias = *(const float2*)(g_bc + col);
        #pragma unroll
        for (int mt = 0; mt < 4; mt++) {
            int row0 = mBase + warpM * 64 + mt * 16 + gid;
            if (row0 < M)
                store_seg(row0, col, c[mt][nt][0] + bias.x, c[mt][nt][1] + bias.y);
            int row1 = row0 + 8;
            if (row1 < M)
                store_seg(row1, col, c[mt][nt][2] + bias.x, c[mt][nt][3] + bias.y);
        }
    }
}

// ---------------- attention: one warp per dst node, depth-2 index prefetch ----------------
__global__ __launch_bounds__(256) void attn_kernel() {
    int warp = (blockIdx.x * blockDim.x + threadIdx.x) >> 5;
    int lane = threadIdx.x & 31;
    if (warp >= N_NODES) return;

    const float* base_q = g_qs + (size_t)warp * 512 + lane * 8;
    float4 q0 = *(const float4*)(base_q);
    float4 q1 = *(const float4*)(base_q + 4);

    float m = -INFINITY, s = 0.f;
    float4 a0 = make_float4(0.f, 0.f, 0.f, 0.f);
    float4 a1 = make_float4(0.f, 0.f, 0.f, 0.f);

    int e0 = g_off[warp], e1 = g_off[warp + 1];

    uint4 kc = make_uint4(0, 0, 0, 0), vc = make_uint4(0, 0, 0, 0);
    int sB = 0;   // src index for edge i+1
    if (e0 < e1) {
        const __half* kvb = g_kv + (size_t)g_psrc[e0] * 512 + lane * 8;
        kc = *(const uint4*)(kvb);
        vc = *(const uint4*)(kvb + 256);
        if (e0 + 1 < e1) sB = g_psrc[e0 + 1];
    }

    for (int i = e0; i < e1; i++) {
        uint4 kcur = kc, vcur = vc;
        // fetch src index two ahead (breaks the index->gather chain)
        int sC = (i + 2 < e1) ? g_psrc[i + 2] : 0;
        // issue K/V gather for edge i+1 using the pre-fetched index
        if (i + 1 < e1) {
            const __half* kvb = g_kv + (size_t)sB * 512 + lane * 8;
            kc = *(const uint4*)(kvb);
            vc = *(const uint4*)(kvb + 256);
        }
        sB = sC;

        float2 k01 = __half22float2(*(const __half2*)&kcur.x);
        float2 k23 = __half22float2(*(const __half2*)&kcur.y);
        float2 k45 = __half22float2(*(const __half2*)&kcur.z);
        float2 k67 = __half22float2(*(const __half2*)&kcur.w);

        float d = q0.x * k01.x + q0.y * k01.y + q0.z * k23.x + q0.w * k23.y
                + q1.x * k45.x + q1.y * k45.y + q1.z * k67.x + q1.w * k67.y;
        d += __shfl_xor_sync(0xFFFFFFFFu, d, 1);
        d += __shfl_xor_sync(0xFFFFFFFFu, d, 2);
        float logit = d * 0.17677669529663687f;   // 1/sqrt(32)

        float mN = fmaxf(m, logit);
        float sc = __expf(m - mN);
        float p  = __expf(logit - mN);
        m = mN;
        s = s * sc + p;

        float2 v01 = __half22float2(*(const __half2*)&vcur.x);
        float2 v23 = __half22float2(*(const __half2*)&vcur.y);
        float2 v45 = __half22float2(*(const __half2*)&vcur.z);
        float2 v67 = __half22float2(*(const __half2*)&vcur.w);

        a0.x = a0.x * sc + p * v01.x; a0.y = a0.y * sc + p * v01.y;
        a0.z = a0.z * sc + p * v23.x; a0.w = a0.w * sc + p * v23.y;
        a1.x = a1.x * sc + p * v45.x; a1.y = a1.y * sc + p * v45.y;
        a1.z = a1.z * sc + p * v67.x; a1.w = a1.w * sc + p * v67.y;
    }

    float inv = 1.f / (s + 1e-16f);
    const float* sb = g_qs + (size_t)warp * 512 + 256 + lane * 8;
    float4 s0 = *(const float4*)(sb);
    float4 s1 = *(const float4*)(sb + 4);
    float r0 = fmaxf(a0.x * inv + s0.x, 0.f);
    float r1 = fmaxf(a0.y * inv + s0.y, 0.f);
    float r2 = fmaxf(a0.z * inv + s0.z, 0.f);
    float r3 = fmaxf(a0.w * inv + s0.w, 0.f);
    float r4 = fmaxf(a1.x * inv + s1.x, 0.f);
    float r5 = fmaxf(a1.y * inv + s1.y, 0.f);
    float r6 = fmaxf(a1.z * inv + s1.z, 0.f);
    float r7 = fmaxf(a1.w * inv + s1.w, 0.f);

    __half* hb = g_hh + (size_t)warp * 256 + lane * 8;
    uint4 packed;
    *(__half2*)&packed.x = __floats2half2_rn(r0, r1);
    *(__half2*)&packed.y = __floats2half2_rn(r2, r3);
    *(__half2*)&packed.z = __floats2half2_rn(r4, r5);
    *(__half2*)&packed.w = __floats2half2_rn(r6, r7);
    *(uint4*)hb = packed;
}

// ---------------- pooling ----------------
__global__ void zero_pool_kernel() {
    int i = blockIdx.x * blockDim.x + threadIdx.x;
    if (i < G_GRAPHS * HC) g_pool[i] = 0.f;
    if (i < G_GRAPHS) g_gcnt[i] = 0;
}

__global__ __launch_bounds__(256) void pool_kernel(const int* __restrict__ batch) {
    int c = threadIdx.x;
    int per = (N_NODES + gridDim.x - 1) / gridDim.x;
    int start = blockIdx.x * per;
    int end = min(N_NODES, start + per);
    if (start >= end) return;
    int cur = batch[start];
    float acc = 0.f;
    int cnt = 0;
    for (int i = start; i < end; i++) {
        int b = batch[i];
        if (b != cur) {
            atomicAdd(&g_pool[cur * HC + c], acc);
            if (c == 0) atomicAdd(&g_gcnt[cur], cnt);
            acc = 0.f; cnt = 0; cur = b;
        }
        acc += __half2float(g_hh[(size_t)i * HC + c]);
        cnt++;
    }
    atomicAdd(&g_pool[cur * HC + c], acc);
    if (c == 0) atomicAdd(&g_gcnt[cur], cnt);
}

__global__ void fc_kernel(const float* __restrict__ Wfc, const float* __restrict__ bfc,
                          float* __restrict__ out) {
    int g = blockIdx.x;
    int o = threadIdx.x;
    __shared__ float p[HC];
    float inv = 1.f / fmaxf((float)g_gcnt[g], 1.f);
    for (int i = o; i < HC; i += OUT_F) p[i] = g_pool[g * HC + i] * inv;
    __syncthreads();
    float acc = bfc[o];
    #pragma unroll 8
    for (int f = 0; f < HC; f++) acc += p[f] * Wfc[f * OUT_F + o];
    out[g * OUT_F + o] = acc;
}

// ---------------- launch ----------------
extern "C" void kernel_launch(void* const* d_in, const int* in_sizes, int n_in,
                              void* d_out, int out_size) {
    const float* x    = (const float*)d_in[0];
    const int*   ei   = (const int*)d_in[1];
    const int*   src  = ei;
    const int*   dst  = ei + N_EDGES;
    const int*   batch = (const int*)d_in[2];
    const float* Wq0 = (const float*)d_in[3];
    const float* bq0 = (const float*)d_in[4];
    const float* Wk0 = (const float*)d_in[5];
    const float* bk0 = (const float*)d_in[6];
    const float* Wv0 = (const float*)d_in[7];
    const float* bv0 = (const float*)d_in[8];
    const float* Ws0 = (const float*)d_in[9];
    const float* bs0 = (const float*)d_in[10];
    const float* Wq  = (const float*)d_in[11];
    const float* bq  = (const float*)d_in[12];
    const float* Wk  = (const float*)d_in[13];
    const float* bk  = (const float*)d_in[14];
    const float* Wv  = (const float*)d_in[15];
    const float* bv  = (const float*)d_in[16];
    const float* Ws  = (const float*)d_in[17];
    const float* bs  = (const float*)d_in[18];
    const float* Wfc = (const float*)d_in[19];
    const float* bfc = (const float*)d_in[20];
    float* out = (float*)d_out;

    const int TB = 256;
    dim3 ggrid(1024 / GBN, (N_NODES + GBM - 1) / GBM);
    int attnBlocks = (N_NODES + 7) / 8;

    __half* xh = nullptr;
    __half* hh = nullptr;
    cudaGetSymbolAddress((void**)&xh, g_xh);
    cudaGetSymbolAddress((void**)&hh, g_hh);

    // Reordered so gemm_tc_kernel is the 4th launch (ncu capture slot).
    xcvt_kernel<<<(N_NODES * IN_F / 2 + TB - 1) / TB, TB>>>(x);                              // 1
    pack_kernel<<<(IN_F * 1024 + TB - 1) / TB, TB>>>(Wq0, Wk0, Wv0, Ws0,
                                                     bq0, bk0, bv0, bs0, IN_F);              // 2
    zero_csr_kernel<<<(N_NODES + TB - 1) / TB, TB>>>();                                      // 3
    gemm_tc_kernel<<<ggrid, 256>>>(xh, N_NODES, IN_F);                                       // 4 (profiled)
    hist_kernel<<<(N_EDGES + TB - 1) / TB, TB>>>(dst);                                       // 5
    scan_kernel<<<1, 1024>>>();                                                              // 6
    scatter_kernel<<<(N_EDGES + TB - 1) / TB, TB>>>(src, dst);                               // 7
    attn_kernel<<<attnBlocks, 256>>>();                                                      // 8

    // layers 1..3 (HC -> HC)
    for (int l = 0; l < NLAYERS - 1; l++) {
        const float* wq = Wq + (size_t)l * HC * HC;
        const float* wk = Wk + (size_t)l * HC * HC;
        const float* wv = Wv + (size_t)l * HC * HC;
        const float* ws = Ws + (size_t)l * HC * HC;
        pack_kernel<<<(HC * 1024 + TB - 1) / TB, TB>>>(wq, wk, wv, ws,
                                                       bq + l * HC, bk + l * HC,
                                                       bv + l * HC, bs + l * HC, HC);
        gemm_tc_kernel<<<ggrid, 256>>>(hh, N_NODES, HC);
        attn_kernel<<<attnBlocks, 256>>>();
    }

    // pooling + fc
    zero_pool_kernel<<<(G_GRAPHS * HC + TB - 1) / TB, TB>>>();
    pool_kernel<<<256, 256>>>(batch);
    fc_kernel<<<G_GRAPHS, OUT_F>>>(Wfc, bfc, out);
}